// round 2
// baseline (speedup 1.0000x reference)
#include <cuda_runtime.h>
#include <math.h>

// ---------------- problem constants ----------------
#define BB    4
#define CDIM  96
#define LL    4096      // 64*64
#define DI    192
#define DS    16
#define RNK   6
#define NDIR  16        // 4 directions * BB

// ---------------- scratch (device globals; no allocation) ----------------
__device__ float g_xn[BB * LL * CDIM];          //  6.3 MB  [b][p][c]
__device__ float g_gate[BB * LL * 4];           //  0.26 MB [b][p][k]
__device__ float g_xz[(size_t)BB * LL * 384];   // 25.2 MB  [b][p][e]  (e>=192 stored as silu(z))
__device__ float g_xc[(size_t)NDIR * LL * DI];  // 50.3 MB  [n][l][d]
__device__ float g_dtm[(size_t)NDIR * LL * RNK];//  1.6 MB  [n][l][r]
__device__ float g_BC[(size_t)NDIR * LL * 32];  //  8.4 MB  [n][l][B0..15,C0..15]
__device__ float g_delta[(size_t)NDIR * LL * DI];//50.3 MB  [n][l][d]
__device__ float g_ycomb[(size_t)BB * LL * DI]; // 12.6 MB  [b][p][d]

// direction pixel map: p_k(l)
__device__ __forceinline__ int pmap(int l, int k) {
    int lr = (k & 2) ? (LL - 1 - l) : l;
    return (k & 1) ? (((lr & 63) << 6) | (lr >> 6)) : lr;
}

// ---------------- K1: layernorm + gate MLP (+ zero ycomb) ----------------
__global__ void __launch_bounds__(128) norm_gate_kernel(
    const float* __restrict__ x, const float* __restrict__ ng, const float* __restrict__ nb,
    const float* __restrict__ w1, const float* __restrict__ b1,
    const float* __restrict__ w2, const float* __restrict__ b2)
{
    __shared__ float xs_s[CDIM][33];
    __shared__ float w1_s[24 * 96];
    const int tid = threadIdx.x;
    const int P0 = blockIdx.x * 32;
    const int b = P0 >> 12, p0 = P0 & 4095;

    // zero ycomb (each block clears its slice: 3145728/512 = 6144)
    {
        size_t base = (size_t)blockIdx.x * 6144;
        for (int i = tid; i < 6144; i += 128) g_ycomb[base + i] = 0.f;
    }
    for (int i = tid; i < 96 * 32; i += 128) {
        int c = i >> 5, pi = i & 31;
        xs_s[c][pi] = x[((size_t)b * 96 + c) * 4096 + p0 + pi];
    }
    for (int i = tid; i < 24 * 96; i += 128) w1_s[i] = w1[i];
    __syncthreads();

    if (tid < 32) {
        const int lane = tid;
        float mu = 0.f;
        #pragma unroll
        for (int c = 0; c < 96; c++) mu += xs_s[c][lane];
        mu *= (1.f / 96.f);
        float var = 0.f;
        #pragma unroll
        for (int c = 0; c < 96; c++) { float dv = xs_s[c][lane] - mu; var += dv * dv; }
        var *= (1.f / 96.f);
        const float inv = rsqrtf(var + 1e-5f);
        #pragma unroll
        for (int c = 0; c < 96; c++)
            xs_s[c][lane] = (xs_s[c][lane] - mu) * inv * ng[c] + nb[c];

        float hbuf[24];
        #pragma unroll 4
        for (int jj = 0; jj < 24; jj++) {
            float s = b1[jj];
            for (int c = 0; c < 96; c++) s += xs_s[c][lane] * w1_s[jj * 96 + c];
            hbuf[jj] = tanhf(s);
        }
        float lg[4];
        #pragma unroll
        for (int q = 0; q < 4; q++) {
            float s = b2[q];
            #pragma unroll
            for (int jj = 0; jj < 24; jj++) s += hbuf[jj] * w2[q * 24 + jj];
            lg[q] = s;
        }
        float m = fmaxf(fmaxf(lg[0], lg[1]), fmaxf(lg[2], lg[3]));
        float e[4], se = 0.f;
        #pragma unroll
        for (int q = 0; q < 4; q++) { e[q] = __expf(lg[q] - m); se += e[q]; }
        float rs = 1.f / se;
        size_t gb = (size_t)(b * 4096 + p0 + lane) * 4;
        #pragma unroll
        for (int q = 0; q < 4; q++) g_gate[gb + q] = e[q] * rs;
    }
    __syncthreads();
    for (int i = tid; i < 32 * 96; i += 128) {
        int pi = i / 96, c = i % 96;
        g_xn[(size_t)(b * 4096 + p0 + pi) * 96 + c] = xs_s[c][pi];
    }
}

// ---------------- generic tiled fp32 GEMM: C[M][N] = A[M][K] * W[N][K]^T ----------------
// MODE 0: A=g_xn,   out -> g_xz   (silu applied for e>=192)      (K=96,  Nvalid=384)
// MODE 1: A=g_xc,   out -> g_dtm / g_BC split                    (K=192, Nvalid=38)
// MODE 2: A=g_ycomb,out -> d_out transposed to (B,C,H,W)         (K=192, Nvalid=96)
template<int KD, int MODE>
__global__ void __launch_bounds__(256) gemm_kernel(
    const float* __restrict__ W, float* __restrict__ Cout, int Nvalid)
{
    __shared__ float As[16][64];
    __shared__ float Ws[16][64];
    const float* A = (MODE == 0) ? g_xn : (MODE == 1) ? g_xc : g_ycomb;

    const int tid = threadIdx.x;
    const int tx = tid & 15, ty = tid >> 4;
    const int m0 = blockIdx.x * 64;
    const int n0 = blockIdx.y * 64;

    const int lm = tid >> 2;            // 0..63
    const int lk = (tid & 3) * 4;       // 0,4,8,12
    const float* Aptr = A + (size_t)(m0 + lm) * KD + lk;
    const int wn = n0 + lm;
    const bool wvalid = (wn < Nvalid);
    const float* Wptr = W + (size_t)wn * KD + lk;

    float acc[4][4];
    #pragma unroll
    for (int i = 0; i < 4; i++)
        #pragma unroll
        for (int j = 0; j < 4; j++) acc[i][j] = 0.f;

    for (int k0 = 0; k0 < KD; k0 += 16) {
        float4 av = *(const float4*)(Aptr + k0);
        float4 wv = wvalid ? *(const float4*)(Wptr + k0) : make_float4(0.f, 0.f, 0.f, 0.f);
        __syncthreads();
        As[lk + 0][lm] = av.x; As[lk + 1][lm] = av.y; As[lk + 2][lm] = av.z; As[lk + 3][lm] = av.w;
        Ws[lk + 0][lm] = wv.x; Ws[lk + 1][lm] = wv.y; Ws[lk + 2][lm] = wv.z; Ws[lk + 3][lm] = wv.w;
        __syncthreads();
        #pragma unroll
        for (int kk = 0; kk < 16; kk++) {
            float4 a4 = *(const float4*)&As[kk][ty << 2];
            float4 w4 = *(const float4*)&Ws[kk][tx << 2];
            float ar[4] = { a4.x, a4.y, a4.z, a4.w };
            float wr[4] = { w4.x, w4.y, w4.z, w4.w };
            #pragma unroll
            for (int i = 0; i < 4; i++)
                #pragma unroll
                for (int j = 0; j < 4; j++) acc[i][j] += ar[i] * wr[j];
        }
    }

    #pragma unroll
    for (int i = 0; i < 4; i++) {
        int r = m0 + (ty << 2) + i;
        #pragma unroll
        for (int j = 0; j < 4; j++) {
            int cn = n0 + (tx << 2) + j;
            float v = acc[i][j];
            if (MODE == 0) {
                if (cn >= 192) v = v / (1.f + __expf(-v));   // silu(z)
                g_xz[(size_t)r * 384 + cn] = v;
            } else if (MODE == 1) {
                if (cn < RNK)      g_dtm[(size_t)r * RNK + cn] = v;
                else if (cn < 38)  g_BC[(size_t)r * 32 + (cn - RNK)] = v;
            } else {
                if (cn < 96) {
                    int bb = r >> 12, p = r & 4095;
                    Cout[((size_t)bb * 96 + cn) * 4096 + p] = v;
                }
            }
        }
    }
}

// ---------------- K3: depthwise causal conv (per direction) + silu ----------------
#define CONV_TL 128
__global__ void __launch_bounds__(192) conv_kernel(
    const float* __restrict__ cw, const float* __restrict__ cb)
{
    const int d = threadIdx.x;
    const int n = blockIdx.y;
    const int l0 = blockIdx.x * CONV_TL;
    const int b = n & 3, k = n >> 2;
    const float w0 = cw[d * 4 + 0], w1 = cw[d * 4 + 1], w2 = cw[d * 4 + 2], w3 = cw[d * 4 + 3];
    const float bias = cb[d];
    const float* xzb = g_xz + (size_t)b * LL * 384 + d;

    float x1 = (l0 - 3 >= 0) ? xzb[(size_t)pmap(l0 - 3, k) * 384] : 0.f;
    float x2 = (l0 - 2 >= 0) ? xzb[(size_t)pmap(l0 - 2, k) * 384] : 0.f;
    float x3 = (l0 - 1 >= 0) ? xzb[(size_t)pmap(l0 - 1, k) * 384] : 0.f;

    #pragma unroll 4
    for (int l = l0; l < l0 + CONV_TL; ++l) {
        float cur = xzb[(size_t)pmap(l, k) * 384];
        float v = bias + w0 * x1 + w1 * x2 + w2 * x3 + w3 * cur;
        v = v / (1.f + __expf(-v));
        g_xc[((size_t)n * LL + l) * DI + d] = v;
        x1 = x2; x2 = x3; x3 = cur;
    }
}

// ---------------- K5: dt_proj + softplus -> delta ----------------
__global__ void __launch_bounds__(256) dtproj_kernel(
    const float* __restrict__ dtw, const float* __restrict__ dtb)
{
    const size_t idx = (size_t)blockIdx.x * 256 + threadIdx.x;   // < NDIR*LL*DI
    const int d = (int)(idx % DI);
    const size_t nl = idx / DI;
    const float* dtr = g_dtm + nl * RNK;
    float s = dtb[d];
    #pragma unroll
    for (int r = 0; r < RNK; r++) s += dtr[r] * dtw[d * RNK + r];
    g_delta[idx] = (s > 20.f) ? s : log1pf(__expf(s));
}

// ---------------- K6: selective scan + fused epilogue + gated scatter ----------------
// 768 warps; warp handles 4 channels (d) of one sequence n; 8 lanes/channel; 2 states/lane.
__global__ void __launch_bounds__(64) scan_kernel(
    const float* __restrict__ A_log, const float* __restrict__ Dp)
{
    const int wid = (int)((blockIdx.x * 64 + threadIdx.x) >> 5);   // 0..767
    const int lane = threadIdx.x & 31;
    const int n = wid / 48;
    const int dbase = (wid % 48) << 2;
    const int g = lane >> 3, j = lane & 7;
    const int d = dbase + g;
    const int b = n & 3, k = n >> 2;
    const float LOG2E = 1.4426950408889634f;

    const float cA0 = -expf(A_log[d * DS + 2 * j]) * LOG2E;
    const float cA1 = -expf(A_log[d * DS + 2 * j + 1]) * LOG2E;
    const float Dd = Dp[dbase + (lane & 3)];

    const float* dlt_p = g_delta + (size_t)n * LL * DI + d;
    const float* xc_p  = g_xc    + (size_t)n * LL * DI + d;
    const float* bc_p  = g_BC    + (size_t)n * LL * 32;
    const float* z_p   = g_xz    + (size_t)b * LL * 384 + 192 + dbase + (lane & 3);
    const float* gt_p  = g_gate  + (size_t)b * LL * 4 + k;
    float* yc_p        = g_ycomb + (size_t)b * LL * DI + dbase + (lane & 3);
    const int src = (lane & 3) << 3;

    float h0 = 0.f, h1 = 0.f;
    #pragma unroll 4
    for (int l = 0; l < LL; ++l) {
        float dlt = dlt_p[(size_t)l * DI];
        float u   = xc_p[(size_t)l * DI];
        const float* bc = bc_p + (size_t)l * 32;
        float2 Bv = *(const float2*)(bc + 2 * j);
        float2 Cv = *(const float2*)(bc + 16 + 2 * j);
        float du = dlt * u;
        h0 = exp2f(dlt * cA0) * h0 + du * Bv.x;
        h1 = exp2f(dlt * cA1) * h1 + du * Bv.y;
        float yp = h0 * Cv.x + h1 * Cv.y;
        yp += __shfl_xor_sync(0xffffffffu, yp, 1);
        yp += __shfl_xor_sync(0xffffffffu, yp, 2);
        yp += __shfl_xor_sync(0xffffffffu, yp, 4);
        float yg = __shfl_sync(0xffffffffu, yp, src);
        float ug = __shfl_sync(0xffffffffu, u, src);
        if (lane < 4) {
            int lr = (k & 2) ? (LL - 1 - l) : l;
            int p  = (k & 1) ? (((lr & 63) << 6) | (lr >> 6)) : lr;
            float zs = z_p[(size_t)p * 384];    // already silu'd
            float gt = gt_p[(size_t)p * 4];
            atomicAdd(yc_p + (size_t)p * DI, (yg + ug * Dd) * (zs * gt));
        }
    }
}

// ---------------- launch ----------------
extern "C" void kernel_launch(void* const* d_in, const int* in_sizes, int n_in,
                              void* d_out, int out_size)
{
    const float* x         = (const float*)d_in[0];
    const float* norm_g    = (const float*)d_in[1];
    const float* norm_b    = (const float*)d_in[2];
    const float* gate_w1   = (const float*)d_in[3];
    const float* gate_b1   = (const float*)d_in[4];
    const float* gate_w2   = (const float*)d_in[5];
    const float* gate_b2   = (const float*)d_in[6];
    const float* in_proj_w = (const float*)d_in[7];
    const float* conv_w    = (const float*)d_in[8];
    const float* conv_b    = (const float*)d_in[9];
    const float* x_proj_w  = (const float*)d_in[10];
    const float* dt_proj_w = (const float*)d_in[11];
    const float* dt_proj_b = (const float*)d_in[12];
    const float* A_log     = (const float*)d_in[13];
    const float* Dvec      = (const float*)d_in[14];
    const float* out_proj_w= (const float*)d_in[15];
    float* out = (float*)d_out;

    // K1: layernorm + gate (also zeroes g_ycomb)
    norm_gate_kernel<<<512, 128>>>(x, norm_g, norm_b, gate_w1, gate_b1, gate_w2, gate_b2);
    // K2: in_proj (shared across directions), silu(z) fused
    gemm_kernel<96, 0><<<dim3(256, 6), 256>>>(in_proj_w, nullptr, 384);
    // K3: causal depthwise conv + silu, per direction
    conv_kernel<<<dim3(LL / CONV_TL, NDIR), 192>>>(conv_w, conv_b);
    // K4: x_proj -> dt, B, C
    gemm_kernel<192, 1><<<dim3(1024, 1), 256>>>(x_proj_w, nullptr, 38);
    // K5: dt_proj + softplus
    dtproj_kernel<<<(NDIR * LL * DI) / 256, 256>>>(dt_proj_w, dt_proj_b);
    // K6: selective scan + fused D/silu(z)/gate + scatter-accumulate
    scan_kernel<<<384, 64>>>(A_log, Dvec);
    // K7: out_proj on combined y, transposed store to (B,C,H,W)
    gemm_kernel<192, 2><<<dim3(256, 2), 256>>>(out_proj_w, out, 96);
}

// round 3
// speedup vs baseline: 5.4348x; 5.4348x over previous
#include <cuda_runtime.h>
#include <math.h>

// ---------------- problem constants ----------------
#define BB    4
#define CDIM  96
#define LL    4096      // 64*64
#define DI    192
#define DS    16
#define RNK   6
#define NDIR  16        // 4 directions * BB
#define CT    64        // chunk length
#define NC    64        // number of chunks

// ---------------- scratch (device globals; no allocation) ----------------
__device__ float g_xn[BB * LL * CDIM];          //  6.3 MB  [b][p][c]
__device__ float g_gate[BB * LL * 4];           //  0.26 MB [b][p][k]
__device__ float g_xz[(size_t)BB * LL * 384];   // 25.2 MB  [b][p][e]  (e>=192 stored as silu(z))
__device__ float g_xc[(size_t)NDIR * LL * DI];  // 50.3 MB  [n][l][d]
__device__ float g_dtm[(size_t)NDIR * LL * RNK];//  1.6 MB  [n][l][r]
__device__ float g_BC[(size_t)NDIR * LL * 32];  //  8.4 MB  [n][l][B0..15,C0..15]
__device__ float g_delta[(size_t)NDIR * LL * DI];//50.3 MB  [n][l][d]
__device__ float g_ycomb[(size_t)BB * LL * DI]; // 12.6 MB  [b][p][d]
__device__ float g_H[(size_t)NDIR * NC * DI * DS]; // 12.6 MB [n][c][d][s]  local end-state, then h_init
__device__ float g_P[(size_t)NDIR * NC * DI * DS]; // 12.6 MB [n][c][d][s]  chunk decay product

// direction pixel map: p_k(l)
__device__ __forceinline__ int pmap(int l, int k) {
    int lr = (k & 2) ? (LL - 1 - l) : l;
    return (k & 1) ? (((lr & 63) << 6) | (lr >> 6)) : lr;
}

// ---------------- K1: layernorm + gate MLP (+ zero ycomb) ----------------
__global__ void __launch_bounds__(128) norm_gate_kernel(
    const float* __restrict__ x, const float* __restrict__ ng, const float* __restrict__ nb,
    const float* __restrict__ w1, const float* __restrict__ b1,
    const float* __restrict__ w2, const float* __restrict__ b2)
{
    __shared__ float xs_s[CDIM][33];
    __shared__ float w1_s[24 * 96];
    const int tid = threadIdx.x;
    const int P0 = blockIdx.x * 32;
    const int b = P0 >> 12, p0 = P0 & 4095;

    {
        size_t base = (size_t)blockIdx.x * 6144;
        for (int i = tid; i < 6144; i += 128) g_ycomb[base + i] = 0.f;
    }
    for (int i = tid; i < 96 * 32; i += 128) {
        int c = i >> 5, pi = i & 31;
        xs_s[c][pi] = x[((size_t)b * 96 + c) * 4096 + p0 + pi];
    }
    for (int i = tid; i < 24 * 96; i += 128) w1_s[i] = w1[i];
    __syncthreads();

    if (tid < 32) {
        const int lane = tid;
        float mu = 0.f;
        #pragma unroll
        for (int c = 0; c < 96; c++) mu += xs_s[c][lane];
        mu *= (1.f / 96.f);
        float var = 0.f;
        #pragma unroll
        for (int c = 0; c < 96; c++) { float dv = xs_s[c][lane] - mu; var += dv * dv; }
        var *= (1.f / 96.f);
        const float inv = rsqrtf(var + 1e-5f);
        #pragma unroll
        for (int c = 0; c < 96; c++)
            xs_s[c][lane] = (xs_s[c][lane] - mu) * inv * ng[c] + nb[c];

        float hbuf[24];
        #pragma unroll 4
        for (int jj = 0; jj < 24; jj++) {
            float s = b1[jj];
            for (int c = 0; c < 96; c++) s += xs_s[c][lane] * w1_s[jj * 96 + c];
            hbuf[jj] = tanhf(s);
        }
        float lg[4];
        #pragma unroll
        for (int q = 0; q < 4; q++) {
            float s = b2[q];
            #pragma unroll
            for (int jj = 0; jj < 24; jj++) s += hbuf[jj] * w2[q * 24 + jj];
            lg[q] = s;
        }
        float m = fmaxf(fmaxf(lg[0], lg[1]), fmaxf(lg[2], lg[3]));
        float e[4], se = 0.f;
        #pragma unroll
        for (int q = 0; q < 4; q++) { e[q] = __expf(lg[q] - m); se += e[q]; }
        float rs = 1.f / se;
        size_t gb = (size_t)(b * 4096 + p0 + lane) * 4;
        #pragma unroll
        for (int q = 0; q < 4; q++) g_gate[gb + q] = e[q] * rs;
    }
    __syncthreads();
    for (int i = tid; i < 32 * 96; i += 128) {
        int pi = i / 96, c = i % 96;
        g_xn[(size_t)(b * 4096 + p0 + pi) * 96 + c] = xs_s[c][pi];
    }
}

// ---------------- generic tiled fp32 GEMM: C[M][N] = A[M][K] * W[N][K]^T ----------------
template<int KD, int MODE>
__global__ void __launch_bounds__(256) gemm_kernel(
    const float* __restrict__ W, float* __restrict__ Cout, int Nvalid)
{
    __shared__ float As[16][64];
    __shared__ float Ws[16][64];
    const float* A = (MODE == 0) ? g_xn : (MODE == 1) ? g_xc : g_ycomb;

    const int tid = threadIdx.x;
    const int tx = tid & 15, ty = tid >> 4;
    const int m0 = blockIdx.x * 64;
    const int n0 = blockIdx.y * 64;

    const int lm = tid >> 2;
    const int lk = (tid & 3) * 4;
    const float* Aptr = A + (size_t)(m0 + lm) * KD + lk;
    const int wn = n0 + lm;
    const bool wvalid = (wn < Nvalid);
    const float* Wptr = W + (size_t)wn * KD + lk;

    float acc[4][4];
    #pragma unroll
    for (int i = 0; i < 4; i++)
        #pragma unroll
        for (int j = 0; j < 4; j++) acc[i][j] = 0.f;

    for (int k0 = 0; k0 < KD; k0 += 16) {
        float4 av = *(const float4*)(Aptr + k0);
        float4 wv = wvalid ? *(const float4*)(Wptr + k0) : make_float4(0.f, 0.f, 0.f, 0.f);
        __syncthreads();
        As[lk + 0][lm] = av.x; As[lk + 1][lm] = av.y; As[lk + 2][lm] = av.z; As[lk + 3][lm] = av.w;
        Ws[lk + 0][lm] = wv.x; Ws[lk + 1][lm] = wv.y; Ws[lk + 2][lm] = wv.z; Ws[lk + 3][lm] = wv.w;
        __syncthreads();
        #pragma unroll
        for (int kk = 0; kk < 16; kk++) {
            float4 a4 = *(const float4*)&As[kk][ty << 2];
            float4 w4 = *(const float4*)&Ws[kk][tx << 2];
            float ar[4] = { a4.x, a4.y, a4.z, a4.w };
            float wr[4] = { w4.x, w4.y, w4.z, w4.w };
            #pragma unroll
            for (int i = 0; i < 4; i++)
                #pragma unroll
                for (int j = 0; j < 4; j++) acc[i][j] += ar[i] * wr[j];
        }
    }

    #pragma unroll
    for (int i = 0; i < 4; i++) {
        int r = m0 + (ty << 2) + i;
        #pragma unroll
        for (int j = 0; j < 4; j++) {
            int cn = n0 + (tx << 2) + j;
            float v = acc[i][j];
            if (MODE == 0) {
                if (cn >= 192) v = v / (1.f + __expf(-v));   // silu(z)
                g_xz[(size_t)r * 384 + cn] = v;
            } else if (MODE == 1) {
                if (cn < RNK)      g_dtm[(size_t)r * RNK + cn] = v;
                else if (cn < 38)  g_BC[(size_t)r * 32 + (cn - RNK)] = v;
            } else {
                if (cn < 96) {
                    int bb = r >> 12, p = r & 4095;
                    Cout[((size_t)bb * 96 + cn) * 4096 + p] = v;
                }
            }
        }
    }
}

// ---------------- K3: depthwise causal conv (per direction) + silu ----------------
#define CONV_TL 128
__global__ void __launch_bounds__(192) conv_kernel(
    const float* __restrict__ cw, const float* __restrict__ cb)
{
    const int d = threadIdx.x;
    const int n = blockIdx.y;
    const int l0 = blockIdx.x * CONV_TL;
    const int b = n & 3, k = n >> 2;
    const float w0 = cw[d * 4 + 0], w1 = cw[d * 4 + 1], w2 = cw[d * 4 + 2], w3 = cw[d * 4 + 3];
    const float bias = cb[d];
    const float* xzb = g_xz + (size_t)b * LL * 384 + d;

    float x1 = (l0 - 3 >= 0) ? xzb[(size_t)pmap(l0 - 3, k) * 384] : 0.f;
    float x2 = (l0 - 2 >= 0) ? xzb[(size_t)pmap(l0 - 2, k) * 384] : 0.f;
    float x3 = (l0 - 1 >= 0) ? xzb[(size_t)pmap(l0 - 1, k) * 384] : 0.f;

    #pragma unroll 4
    for (int l = l0; l < l0 + CONV_TL; ++l) {
        float cur = xzb[(size_t)pmap(l, k) * 384];
        float v = bias + w0 * x1 + w1 * x2 + w2 * x3 + w3 * cur;
        v = v / (1.f + __expf(-v));
        g_xc[((size_t)n * LL + l) * DI + d] = v;
        x1 = x2; x2 = x3; x3 = cur;
    }
}

// ---------------- K5: dt_proj + softplus -> delta ----------------
__global__ void __launch_bounds__(256) dtproj_kernel(
    const float* __restrict__ dtw, const float* __restrict__ dtb)
{
    const size_t idx = (size_t)blockIdx.x * 256 + threadIdx.x;
    const int d = (int)(idx % DI);
    const size_t nl = idx / DI;
    const float* dtr = g_dtm + nl * RNK;
    float s = dtb[d];
    #pragma unroll
    for (int r = 0; r < RNK; r++) s += dtr[r] * dtw[d * RNK + r];
    g_delta[idx] = (s > 20.f) ? s : log1pf(__expf(s));
}

// ---------------- chunked selective scan ----------------
// Block: (chunk c, dgroup dg, seq n). 128 threads = 4 warps; warp w covers
// d = dg*8 + {2w, 2w+1}, 16 s-lanes per d.

// Pass A: local scan from h=0 within chunk; store end-state H and decay product P.
__global__ void __launch_bounds__(128) scanA_kernel(const float* __restrict__ A_log)
{
    __shared__ float sd[CT][8], su[CT][8], sB[CT][16];
    const int tid = threadIdx.x;
    const int c = blockIdx.x, dg = blockIdx.y, n = blockIdx.z;
    const int l0 = c * CT, d0 = dg * 8;

    for (int i = tid; i < CT * 8; i += 128) {
        int l = i >> 3, dd = i & 7;
        size_t off = ((size_t)n * LL + l0 + l) * DI + d0 + dd;
        sd[l][dd] = g_delta[off];
        su[l][dd] = g_xc[off];
    }
    for (int i = tid; i < CT * 16; i += 128) {
        int l = i >> 4, s = i & 15;
        sB[l][s] = g_BC[((size_t)n * LL + l0 + l) * 32 + s];
    }
    const int ln = tid & 31, w = tid >> 5;
    const int s = ln & 15, dloc = (w << 1) | (ln >> 4);
    const int d = d0 + dloc;
    const float cA = -expf(A_log[d * DS + s]) * 1.4426950408889634f;
    __syncthreads();

    float h = 0.f, P = 1.f;
    #pragma unroll 8
    for (int l = 0; l < CT; ++l) {
        float dlt = sd[l][dloc];
        float a = exp2f(dlt * cA);
        h = a * h + (dlt * su[l][dloc]) * sB[l][s];
        P *= a;
    }
    size_t o = ((size_t)(n * NC + c)) * (DI * DS) + d * DS + s;
    g_H[o] = h;
    g_P[o] = P;
}

// Pass B: sequential scan over 64 chunk summaries per (n,d,s); overwrite g_H with h_init.
__global__ void __launch_bounds__(256) scanB_kernel()
{
    const int gid = blockIdx.x * 256 + threadIdx.x;     // < 16*3072
    const int n = gid / (DI * DS);
    const int ds = gid - n * (DI * DS);
    size_t base = (size_t)n * NC * (DI * DS) + ds;
    float h = 0.f;
    #pragma unroll 4
    for (int cc = 0; cc < NC; ++cc) {
        size_t a = base + (size_t)cc * (DI * DS);
        float Pv = g_P[a], Hv = g_H[a];
        g_H[a] = h;                      // h entering chunk cc
        h = Pv * h + Hv;
    }
}

// Pass C: recompute with correct h_init, reduce over s, fused epilogue + gated scatter.
__global__ void __launch_bounds__(128) scanC_kernel(
    const float* __restrict__ A_log, const float* __restrict__ Dp)
{
    __shared__ float sd[CT][8], su[CT][8], sBC[CT][32], sz[CT][8], sg[CT];
    __shared__ int sp[CT];
    const int tid = threadIdx.x;
    const int c = blockIdx.x, dg = blockIdx.y, n = blockIdx.z;
    const int l0 = c * CT, d0 = dg * 8;
    const int b = n & 3, k = n >> 2;

    for (int i = tid; i < CT * 8; i += 128) {
        int l = i >> 3, dd = i & 7;
        size_t off = ((size_t)n * LL + l0 + l) * DI + d0 + dd;
        sd[l][dd] = g_delta[off];
        su[l][dd] = g_xc[off];
        int p = pmap(l0 + l, k);
        sz[l][dd] = g_xz[((size_t)b * LL + p) * 384 + 192 + d0 + dd];
    }
    for (int i = tid; i < CT * 32; i += 128) {
        int l = i >> 5, s = i & 31;
        sBC[l][s] = g_BC[((size_t)n * LL + l0 + l) * 32 + s];
    }
    if (tid < CT) {
        int p = pmap(l0 + tid, k);
        sp[tid] = p;
        sg[tid] = g_gate[((size_t)b * LL + p) * 4 + k];
    }
    const int ln = tid & 31, w = tid >> 5;
    const int s = ln & 15, dloc = (w << 1) | (ln >> 4);
    const int d = d0 + dloc;
    const float cA = -expf(A_log[d * DS + s]) * 1.4426950408889634f;
    const float Dd = Dp[d];
    __syncthreads();

    float h = g_H[((size_t)(n * NC + c)) * (DI * DS) + d * DS + s];
    float* ycb = g_ycomb + (size_t)b * LL * DI + d;

    #pragma unroll 4
    for (int l = 0; l < CT; ++l) {
        float dlt = sd[l][dloc];
        float u   = su[l][dloc];
        float a = exp2f(dlt * cA);
        h = a * h + (dlt * u) * sBC[l][s];
        float y = h * sBC[l][16 + s];
        y += __shfl_xor_sync(0xffffffffu, y, 1);
        y += __shfl_xor_sync(0xffffffffu, y, 2);
        y += __shfl_xor_sync(0xffffffffu, y, 4);
        y += __shfl_xor_sync(0xffffffffu, y, 8);
        if (s == 0) {
            float v = (y + u * Dd) * sz[l][dloc] * sg[l];
            atomicAdd(ycb + (size_t)sp[l] * DI, v);
        }
    }
}

// ---------------- launch ----------------
extern "C" void kernel_launch(void* const* d_in, const int* in_sizes, int n_in,
                              void* d_out, int out_size)
{
    const float* x         = (const float*)d_in[0];
    const float* norm_g    = (const float*)d_in[1];
    const float* norm_b    = (const float*)d_in[2];
    const float* gate_w1   = (const float*)d_in[3];
    const float* gate_b1   = (const float*)d_in[4];
    const float* gate_w2   = (const float*)d_in[5];
    const float* gate_b2   = (const float*)d_in[6];
    const float* in_proj_w = (const float*)d_in[7];
    const float* conv_w    = (const float*)d_in[8];
    const float* conv_b    = (const float*)d_in[9];
    const float* x_proj_w  = (const float*)d_in[10];
    const float* dt_proj_w = (const float*)d_in[11];
    const float* dt_proj_b = (const float*)d_in[12];
    const float* A_log     = (const float*)d_in[13];
    const float* Dvec      = (const float*)d_in[14];
    const float* out_proj_w= (const float*)d_in[15];
    float* out = (float*)d_out;

    norm_gate_kernel<<<512, 128>>>(x, norm_g, norm_b, gate_w1, gate_b1, gate_w2, gate_b2);
    gemm_kernel<96, 0><<<dim3(256, 6), 256>>>(in_proj_w, nullptr, 384);
    conv_kernel<<<dim3(LL / CONV_TL, NDIR), 192>>>(conv_w, conv_b);
    gemm_kernel<192, 1><<<dim3(1024, 1), 256>>>(x_proj_w, nullptr, 38);
    dtproj_kernel<<<(NDIR * LL * DI) / 256, 256>>>(dt_proj_w, dt_proj_b);
    // chunked scan: local pass -> chunk-summary scan -> final pass w/ fused epilogue
    scanA_kernel<<<dim3(NC, 24, NDIR), 128>>>(A_log);
    scanB_kernel<<<(NDIR * DI * DS) / 256, 256>>>();
    scanC_kernel<<<dim3(NC, 24, NDIR), 128>>>(A_log, Dvec);
    gemm_kernel<192, 2><<<dim3(256, 2), 256>>>(out_proj_w, out, 96);
}

// round 4
// speedup vs baseline: 5.5281x; 1.0172x over previous
#include <cuda_runtime.h>
#include <math.h>

// ---------------- problem constants ----------------
#define BB    4
#define CDIM  96
#define LL    4096      // 64*64
#define DI    192
#define DS    16
#define RNK   6
#define NDIR  16        // 4 directions * BB
#define CT    64        // chunk length
#define NC    64        // number of chunks

// ---------------- scratch (device globals; no allocation) ----------------
__device__ float g_xn[BB * LL * CDIM];            // [b][p][c]
__device__ float g_gate[BB * LL * 4];             // [b][p][k]
__device__ float g_xz[(size_t)BB * LL * 384];     // [b][p][e] (e>=192 = silu(z))
__device__ float g_xcT[(size_t)NDIR * DI * LL];   // [n][d][l]  (transposed!)
__device__ float g_dltT[(size_t)NDIR * DI * LL];  // [n][d][l]  (transposed!)
__device__ float g_dtm[(size_t)NDIR * LL * RNK];  // [n][l][r]
__device__ float g_BC[(size_t)NDIR * LL * 32];    // [n][l][B0..15,C0..15]
__device__ float g_ycomb[(size_t)BB * LL * DI];   // [b][p][d]
__device__ float g_H[(size_t)NDIR * NC * DI * DS];// [n][c][d][s]
__device__ float g_P[(size_t)NDIR * NC * DI * DS];// [n][c][d][s]

__device__ __forceinline__ int pmap(int l, int k) {
    int lr = (k & 2) ? (LL - 1 - l) : l;
    return (k & 1) ? (((lr & 63) << 6) | (lr >> 6)) : lr;
}

// ---------------- K1: layernorm + gate MLP (+ zero ycomb) ----------------
__global__ void __launch_bounds__(128) norm_gate_kernel(
    const float* __restrict__ x, const float* __restrict__ ng, const float* __restrict__ nb,
    const float* __restrict__ w1, const float* __restrict__ b1,
    const float* __restrict__ w2, const float* __restrict__ b2)
{
    __shared__ float xs_s[CDIM][33];
    __shared__ float w1_s[24 * 96];
    const int tid = threadIdx.x;
    const int P0 = blockIdx.x * 32;
    const int b = P0 >> 12, p0 = P0 & 4095;

    {
        size_t base = (size_t)blockIdx.x * 6144;
        for (int i = tid; i < 6144; i += 128) g_ycomb[base + i] = 0.f;
    }
    for (int i = tid; i < 96 * 32; i += 128) {
        int c = i >> 5, pi = i & 31;
        xs_s[c][pi] = x[((size_t)b * 96 + c) * 4096 + p0 + pi];
    }
    for (int i = tid; i < 24 * 96; i += 128) w1_s[i] = w1[i];
    __syncthreads();

    if (tid < 32) {
        const int lane = tid;
        float mu = 0.f;
        #pragma unroll
        for (int c = 0; c < 96; c++) mu += xs_s[c][lane];
        mu *= (1.f / 96.f);
        float var = 0.f;
        #pragma unroll
        for (int c = 0; c < 96; c++) { float dv = xs_s[c][lane] - mu; var += dv * dv; }
        var *= (1.f / 96.f);
        const float inv = rsqrtf(var + 1e-5f);
        #pragma unroll
        for (int c = 0; c < 96; c++)
            xs_s[c][lane] = (xs_s[c][lane] - mu) * inv * ng[c] + nb[c];

        float hbuf[24];
        #pragma unroll 4
        for (int jj = 0; jj < 24; jj++) {
            float s = b1[jj];
            for (int c = 0; c < 96; c++) s += xs_s[c][lane] * w1_s[jj * 96 + c];
            hbuf[jj] = tanhf(s);
        }
        float lg[4];
        #pragma unroll
        for (int q = 0; q < 4; q++) {
            float s = b2[q];
            #pragma unroll
            for (int jj = 0; jj < 24; jj++) s += hbuf[jj] * w2[q * 24 + jj];
            lg[q] = s;
        }
        float m = fmaxf(fmaxf(lg[0], lg[1]), fmaxf(lg[2], lg[3]));
        float e[4], se = 0.f;
        #pragma unroll
        for (int q = 0; q < 4; q++) { e[q] = __expf(lg[q] - m); se += e[q]; }
        float rs = 1.f / se;
        size_t gb = (size_t)(b * 4096 + p0 + lane) * 4;
        #pragma unroll
        for (int q = 0; q < 4; q++) g_gate[gb + q] = e[q] * rs;
    }
    __syncthreads();
    for (int i = tid; i < 32 * 96; i += 128) {
        int pi = i / 96, c = i % 96;
        g_xn[(size_t)(b * 4096 + p0 + pi) * 96 + c] = xs_s[c][pi];
    }
}

// ---------------- tiled fp32 GEMM: C[M][N] = A[M][K] * W[N][K]^T ----------------
// MODE 0: A=g_xn (row-major [m][96]),  out -> g_xz (silu for e>=192)
// MODE 1: A=g_xcT (TRANSPOSED [n][d][l], i.e. A^T[k][m]), out -> g_dtm / g_BC
// MODE 2: A=g_ycomb (row-major [m][192]), out -> d_out transposed to (B,C,H,W)
template<int KD, int MODE>
__global__ void __launch_bounds__(256) gemm_kernel(
    const float* __restrict__ W, float* __restrict__ Cout, int Nvalid)
{
    __shared__ float As[16][64];
    __shared__ float Ws[16][64];

    const int tid = threadIdx.x;
    const int tx = tid & 15, ty = tid >> 4;
    const int m0 = blockIdx.x * 64;
    const int n0 = blockIdx.y * 64;

    const int lm = tid >> 2;
    const int lk = (tid & 3) * 4;
    const float* Aptr = nullptr;
    if (MODE == 0) Aptr = g_xn    + (size_t)(m0 + lm) * KD + lk;
    if (MODE == 2) Aptr = g_ycomb + (size_t)(m0 + lm) * KD + lk;
    // TRANSA loader indices (MODE 1)
    const int arow = tid >> 4;           // k within tile (0..15)
    const int acol = (tid & 15) << 2;    // m within tile (0,4,..,60)
    const float* ATptr = g_xcT + (size_t)(m0 >> 12) * DI * LL + (m0 & 4095) + acol;

    const int wn = n0 + lm;
    const bool wvalid = (wn < Nvalid);
    const float* Wptr = W + (size_t)wn * KD + lk;

    float acc[4][4];
    #pragma unroll
    for (int i = 0; i < 4; i++)
        #pragma unroll
        for (int j = 0; j < 4; j++) acc[i][j] = 0.f;

    for (int k0 = 0; k0 < KD; k0 += 16) {
        float4 wv = wvalid ? *(const float4*)(Wptr + k0) : make_float4(0.f, 0.f, 0.f, 0.f);
        if (MODE == 1) {
            float4 av = *(const float4*)(ATptr + (size_t)(k0 + arow) * LL);
            __syncthreads();
            *(float4*)&As[arow][acol] = av;
        } else {
            float4 av = *(const float4*)(Aptr + k0);
            __syncthreads();
            As[lk + 0][lm] = av.x; As[lk + 1][lm] = av.y; As[lk + 2][lm] = av.z; As[lk + 3][lm] = av.w;
        }
        Ws[lk + 0][lm] = wv.x; Ws[lk + 1][lm] = wv.y; Ws[lk + 2][lm] = wv.z; Ws[lk + 3][lm] = wv.w;
        __syncthreads();
        #pragma unroll
        for (int kk = 0; kk < 16; kk++) {
            float4 a4 = *(const float4*)&As[kk][ty << 2];
            float4 w4 = *(const float4*)&Ws[kk][tx << 2];
            float ar[4] = { a4.x, a4.y, a4.z, a4.w };
            float wr[4] = { w4.x, w4.y, w4.z, w4.w };
            #pragma unroll
            for (int i = 0; i < 4; i++)
                #pragma unroll
                for (int j = 0; j < 4; j++) acc[i][j] += ar[i] * wr[j];
        }
    }

    #pragma unroll
    for (int i = 0; i < 4; i++) {
        int r = m0 + (ty << 2) + i;
        #pragma unroll
        for (int j = 0; j < 4; j++) {
            int cn = n0 + (tx << 2) + j;
            float v = acc[i][j];
            if (MODE == 0) {
                if (cn >= 192) v = v / (1.f + __expf(-v));   // silu(z)
                g_xz[(size_t)r * 384 + cn] = v;
            } else if (MODE == 1) {
                if (cn < RNK)      g_dtm[(size_t)r * RNK + cn] = v;
                else if (cn < 38)  g_BC[(size_t)r * 32 + (cn - RNK)] = v;
            } else {
                if (cn < 96) {
                    int bb = r >> 12, p = r & 4095;
                    Cout[((size_t)bb * 96 + cn) * 4096 + p] = v;
                }
            }
        }
    }
}

// ---------------- K3: depthwise causal conv + silu, transposed output ----------------
#define CONV_TL 32
__global__ void __launch_bounds__(192) conv_kernel(
    const float* __restrict__ cw, const float* __restrict__ cb)
{
    __shared__ float sbuf[DI][CONV_TL + 1];
    const int d = threadIdx.x;
    const int n = blockIdx.y;
    const int l0 = blockIdx.x * CONV_TL;
    const int b = n & 3, k = n >> 2;
    const float w0 = cw[d * 4 + 0], w1 = cw[d * 4 + 1], w2 = cw[d * 4 + 2], w3 = cw[d * 4 + 3];
    const float bias = cb[d];
    const float* xzb = g_xz + (size_t)b * LL * 384 + d;

    float x1 = (l0 - 3 >= 0) ? xzb[(size_t)pmap(l0 - 3, k) * 384] : 0.f;
    float x2 = (l0 - 2 >= 0) ? xzb[(size_t)pmap(l0 - 2, k) * 384] : 0.f;
    float x3 = (l0 - 1 >= 0) ? xzb[(size_t)pmap(l0 - 1, k) * 384] : 0.f;

    #pragma unroll 4
    for (int l = 0; l < CONV_TL; ++l) {
        float cur = xzb[(size_t)pmap(l0 + l, k) * 384];
        float v = bias + w0 * x1 + w1 * x2 + w2 * x3 + w3 * cur;
        v = v / (1.f + __expf(-v));
        sbuf[d][l] = v;
        x1 = x2; x2 = x3; x3 = cur;
    }
    __syncthreads();
    // coalesced transposed write: rows of 32 floats
    float* dst = g_xcT + (size_t)n * DI * LL + l0;
    for (int i = threadIdx.x; i < DI * CONV_TL; i += 192) {
        int dd = i >> 5, l2 = i & 31;
        dst[(size_t)dd * LL + l2] = sbuf[dd][l2];
    }
}

// ---------------- K5: dt_proj + softplus -> delta (transposed) ----------------
__global__ void __launch_bounds__(256) dtproj_kernel(
    const float* __restrict__ dtw, const float* __restrict__ dtb)
{
    const size_t idx = (size_t)blockIdx.x * 256 + threadIdx.x;   // n*DI*LL + d*LL + l
    const int n = (int)(idx / (DI * LL));
    const int rem = (int)(idx - (size_t)n * (DI * LL));
    const int d = rem >> 12;        // /LL
    const int l = rem & 4095;
    const float* dtr = g_dtm + ((size_t)n * LL + l) * RNK;
    float s = dtb[d];
    #pragma unroll
    for (int r = 0; r < RNK; r++) s += dtr[r] * dtw[d * RNK + r];
    g_dltT[idx] = (s > 20.f) ? s : log1pf(__expf(s));
}

// ---------------- chunked selective scan ----------------
// Block (c, dg, n): 128 threads = 4 warps; warp w covers d = dg*8 + {2w,2w+1}, 16 s-lanes per d.

// Pass A: local scan from h=0; store end-state H and decay product P = exp2(cA*sum_dlt).
__global__ void __launch_bounds__(128) scanA_kernel(const float* __restrict__ A_log)
{
    __shared__ float2 sdu[8][CT];
    __shared__ float sB[CT][16];
    const int tid = threadIdx.x;
    const int c = blockIdx.x, dg = blockIdx.y, n = blockIdx.z;
    const int l0 = c * CT, d0 = dg * 8;

    for (int i = tid; i < 8 * CT; i += 128) {
        int dd = i >> 6, l = i & 63;
        size_t off = (size_t)n * DI * LL + (size_t)(d0 + dd) * LL + l0 + l;
        sdu[dd][l] = make_float2(g_dltT[off], g_xcT[off]);
    }
    for (int i = tid; i < CT * 16; i += 128) {
        int l = i >> 4, s = i & 15;
        sB[l][s] = g_BC[((size_t)n * LL + l0 + l) * 32 + s];
    }
    const int ln = tid & 31, w = tid >> 5;
    const int s = ln & 15, dloc = (w << 1) | (ln >> 4);
    const int d = d0 + dloc;
    const float cA = -expf(A_log[d * DS + s]) * 1.4426950408889634f;
    __syncthreads();

    float h = 0.f, S = 0.f;
    #pragma unroll 8
    for (int l = 0; l < CT; ++l) {
        float2 du = sdu[dloc][l];
        float a = exp2f(du.x * cA);
        h = a * h + (du.x * du.y) * sB[l][s];
        S += du.x;
    }
    size_t o = ((size_t)(n * NC + c)) * (DI * DS) + d * DS + s;
    g_H[o] = h;
    g_P[o] = exp2f(cA * S);
}

// Pass B: scan 64 chunk summaries per (n,d,s); overwrite g_H with h_init.
__global__ void __launch_bounds__(256) scanB_kernel()
{
    const int gid = blockIdx.x * 256 + threadIdx.x;     // < 16*3072
    const int n = gid / (DI * DS);
    const int ds = gid - n * (DI * DS);
    size_t base = (size_t)n * NC * (DI * DS) + ds;
    float h = 0.f;
    #pragma unroll 4
    for (int cc = 0; cc < NC; ++cc) {
        size_t a = base + (size_t)cc * (DI * DS);
        float Pv = g_P[a], Hv = g_H[a];
        g_H[a] = h;
        h = Pv * h + Hv;
    }
}

// Pass C: recompute with correct h_init, reduce over s, fused epilogue + gated scatter.
__global__ void __launch_bounds__(128) scanC_kernel(
    const float* __restrict__ A_log, const float* __restrict__ Dp)
{
    __shared__ float2 sdu[8][CT];
    __shared__ float sBC[CT][32];
    __shared__ float sz[CT][8];
    __shared__ float sg[CT];
    __shared__ int sp[CT];
    const int tid = threadIdx.x;
    const int c = blockIdx.x, dg = blockIdx.y, n = blockIdx.z;
    const int l0 = c * CT, d0 = dg * 8;
    const int b = n & 3, k = n >> 2;

    for (int i = tid; i < 8 * CT; i += 128) {
        int dd = i >> 6, l = i & 63;
        size_t off = (size_t)n * DI * LL + (size_t)(d0 + dd) * LL + l0 + l;
        sdu[dd][l] = make_float2(g_dltT[off], g_xcT[off]);
        int p = pmap(l0 + l, k);
        sz[l][dd] = g_xz[((size_t)b * LL + p) * 384 + 192 + d0 + dd];
    }
    for (int i = tid; i < CT * 32; i += 128) {
        int l = i >> 5, s = i & 31;
        sBC[l][s] = g_BC[((size_t)n * LL + l0 + l) * 32 + s];
    }
    if (tid < CT) {
        int p = pmap(l0 + tid, k);
        sp[tid] = p;
        sg[tid] = g_gate[((size_t)b * LL + p) * 4 + k];
    }
    const int ln = tid & 31, w = tid >> 5;
    const int s = ln & 15, dloc = (w << 1) | (ln >> 4);
    const int d = d0 + dloc;
    const float cA = -expf(A_log[d * DS + s]) * 1.4426950408889634f;
    const float Dd = Dp[d];
    __syncthreads();

    float h = g_H[((size_t)(n * NC + c)) * (DI * DS) + d * DS + s];
    float* ycb = g_ycomb + (size_t)b * LL * DI + d;

    #pragma unroll 4
    for (int l = 0; l < CT; ++l) {
        float2 du = sdu[dloc][l];
        float a = exp2f(du.x * cA);
        h = a * h + (du.x * du.y) * sBC[l][s];
        float y = h * sBC[l][16 + s];
        y += __shfl_xor_sync(0xffffffffu, y, 1);
        y += __shfl_xor_sync(0xffffffffu, y, 2);
        y += __shfl_xor_sync(0xffffffffu, y, 4);
        y += __shfl_xor_sync(0xffffffffu, y, 8);
        if (s == 0) {
            float v = (y + du.y * Dd) * sz[l][dloc] * sg[l];
            atomicAdd(ycb + (size_t)sp[l] * DI, v);
        }
    }
}

// ---------------- launch ----------------
extern "C" void kernel_launch(void* const* d_in, const int* in_sizes, int n_in,
                              void* d_out, int out_size)
{
    const float* x         = (const float*)d_in[0];
    const float* norm_g    = (const float*)d_in[1];
    const float* norm_b    = (const float*)d_in[2];
    const float* gate_w1   = (const float*)d_in[3];
    const float* gate_b1   = (const float*)d_in[4];
    const float* gate_w2   = (const float*)d_in[5];
    const float* gate_b2   = (const float*)d_in[6];
    const float* in_proj_w = (const float*)d_in[7];
    const float* conv_w    = (const float*)d_in[8];
    const float* conv_b    = (const float*)d_in[9];
    const float* x_proj_w  = (const float*)d_in[10];
    const float* dt_proj_w = (const float*)d_in[11];
    const float* dt_proj_b = (const float*)d_in[12];
    const float* A_log     = (const float*)d_in[13];
    const float* Dvec      = (const float*)d_in[14];
    const float* out_proj_w= (const float*)d_in[15];
    float* out = (float*)d_out;

    norm_gate_kernel<<<512, 128>>>(x, norm_g, norm_b, gate_w1, gate_b1, gate_w2, gate_b2);
    gemm_kernel<96, 0><<<dim3(256, 6), 256>>>(in_proj_w, nullptr, 384);
    conv_kernel<<<dim3(LL / CONV_TL, NDIR), 192>>>(conv_w, conv_b);
    gemm_kernel<192, 1><<<dim3(1024, 1), 256>>>(x_proj_w, nullptr, 38);
    dtproj_kernel<<<(NDIR * DI * LL) / 256, 256>>>(dt_proj_w, dt_proj_b);
    scanA_kernel<<<dim3(NC, 24, NDIR), 128>>>(A_log);
    scanB_kernel<<<(NDIR * DI * DS) / 256, 256>>>();
    scanC_kernel<<<dim3(NC, 24, NDIR), 128>>>(A_log, Dvec);
    gemm_kernel<192, 2><<<dim3(256, 2), 256>>>(out_proj_w, out, 96);
}

// round 5
// speedup vs baseline: 6.7840x; 1.2272x over previous
#include <cuda_runtime.h>
#include <cuda_fp16.h>
#include <math.h>

// ---------------- problem constants ----------------
#define BB    4
#define CDIM  96
#define LL    4096      // 64*64
#define DI    192
#define DS    16
#define RNK   6
#define NDIR  16        // 4 directions * BB
#define CT    64        // chunk length
#define NC    64        // number of chunks

// ---------------- scratch (device globals; no allocation) ----------------
__device__ float  g_xn[BB * LL * CDIM];             // [b][p][c]
__device__ float  g_gateT[(size_t)NDIR * LL];       // [n][l]  gate in scan order
__device__ float  g_xz[(size_t)BB * LL * 384];      // [b][p][e] (e>=192 = silu(z))
__device__ __half g_xcT[(size_t)NDIR * DI * LL];    // [n][d][l]  fp16
__device__ __half g_dltT[(size_t)NDIR * DI * LL];   // [n][d][l]  fp16
__device__ float  g_dtm[(size_t)NDIR * LL * RNK];   // [n][l][r]
__device__ float  g_BC[(size_t)NDIR * LL * 32];     // [n][l][B0..15,C0..15]
__device__ float  g_ycomb[(size_t)BB * LL * DI];    // [b][p][d]
__device__ float  g_H[(size_t)NDIR * NC * DI * DS]; // [n][c][d][s]
__device__ float  g_P[(size_t)NDIR * NC * DI * DS]; // [n][c][d][s]

__device__ __forceinline__ int pmap(int l, int k) {
    int lr = (k & 2) ? (LL - 1 - l) : l;
    return (k & 1) ? (((lr & 63) << 6) | (lr >> 6)) : lr;
}

// ---------------- K1: layernorm + gate MLP (+ zero ycomb, scatter gateT) ----------------
__global__ void __launch_bounds__(128) norm_gate_kernel(
    const float* __restrict__ x, const float* __restrict__ ng, const float* __restrict__ nb,
    const float* __restrict__ w1, const float* __restrict__ b1,
    const float* __restrict__ w2, const float* __restrict__ b2)
{
    __shared__ float xs_s[CDIM][33];
    __shared__ float w1_s[24 * 96];
    const int tid = threadIdx.x;
    const int P0 = blockIdx.x * 32;
    const int b = P0 >> 12, p0 = P0 & 4095;

    {
        size_t base = (size_t)blockIdx.x * 6144;
        for (int i = tid; i < 6144; i += 128) g_ycomb[base + i] = 0.f;
    }
    for (int i = tid; i < 96 * 32; i += 128) {
        int c = i >> 5, pi = i & 31;
        xs_s[c][pi] = x[((size_t)b * 96 + c) * 4096 + p0 + pi];
    }
    for (int i = tid; i < 24 * 96; i += 128) w1_s[i] = w1[i];
    __syncthreads();

    if (tid < 32) {
        const int lane = tid;
        float mu = 0.f;
        #pragma unroll
        for (int c = 0; c < 96; c++) mu += xs_s[c][lane];
        mu *= (1.f / 96.f);
        float var = 0.f;
        #pragma unroll
        for (int c = 0; c < 96; c++) { float dv = xs_s[c][lane] - mu; var += dv * dv; }
        var *= (1.f / 96.f);
        const float inv = rsqrtf(var + 1e-5f);
        #pragma unroll
        for (int c = 0; c < 96; c++)
            xs_s[c][lane] = (xs_s[c][lane] - mu) * inv * ng[c] + nb[c];

        float hbuf[24];
        #pragma unroll 4
        for (int jj = 0; jj < 24; jj++) {
            float s = b1[jj];
            for (int c = 0; c < 96; c++) s += xs_s[c][lane] * w1_s[jj * 96 + c];
            hbuf[jj] = tanhf(s);
        }
        float lg[4];
        #pragma unroll
        for (int q = 0; q < 4; q++) {
            float s = b2[q];
            #pragma unroll
            for (int jj = 0; jj < 24; jj++) s += hbuf[jj] * w2[q * 24 + jj];
            lg[q] = s;
        }
        float m = fmaxf(fmaxf(lg[0], lg[1]), fmaxf(lg[2], lg[3]));
        float e[4], se = 0.f;
        #pragma unroll
        for (int q = 0; q < 4; q++) { e[q] = __expf(lg[q] - m); se += e[q]; }
        float rs = 1.f / se;
        const int p = p0 + lane;
        #pragma unroll
        for (int q = 0; q < 4; q++) {
            int l = pmap(p, q);     // involution: l such that pmap(l,q)=p
            g_gateT[(size_t)(q * 4 + b) * LL + l] = e[q] * rs;
        }
    }
    __syncthreads();
    for (int i = tid; i < 32 * 96; i += 128) {
        int pi = i / 96, c = i % 96;
        g_xn[(size_t)(b * 4096 + p0 + pi) * 96 + c] = xs_s[c][pi];
    }
}

// ---------------- tiled fp32 GEMM: C[M][N] = A[M][K] * W[N][K]^T ----------------
// MODE 0: A=g_xn,  out -> g_xz (silu for e>=192)
// MODE 1: A=g_xcT (fp16, TRANSPOSED [n][d][l]), out -> g_dtm / g_BC
// MODE 2: A=g_ycomb ⊙ silu(z), out -> d_out transposed to (B,C,H,W)
template<int KD, int MODE>
__global__ void __launch_bounds__(256) gemm_kernel(
    const float* __restrict__ W, float* __restrict__ Cout, int Nvalid)
{
    __shared__ float As[16][64];
    __shared__ float Ws[16][64];

    const int tid = threadIdx.x;
    const int tx = tid & 15, ty = tid >> 4;
    const int m0 = blockIdx.x * 64;
    const int n0 = blockIdx.y * 64;

    const int lm = tid >> 2;
    const int lk = (tid & 3) * 4;
    const float* Aptr = nullptr;
    const float* Zptr = nullptr;
    if (MODE == 0) Aptr = g_xn    + (size_t)(m0 + lm) * KD + lk;
    if (MODE == 2) {
        Aptr = g_ycomb + (size_t)(m0 + lm) * KD + lk;
        Zptr = g_xz + (size_t)(m0 + lm) * 384 + 192 + lk;
    }
    const int arow = tid >> 4;           // k within tile (0..15)
    const int acol = (tid & 15) << 2;    // m within tile
    const __half* ATptr = g_xcT + (size_t)(m0 >> 12) * DI * LL + (m0 & 4095) + acol;

    const int wn = n0 + lm;
    const bool wvalid = (wn < Nvalid);
    const float* Wptr = W + (size_t)wn * KD + lk;

    float acc[4][4];
    #pragma unroll
    for (int i = 0; i < 4; i++)
        #pragma unroll
        for (int j = 0; j < 4; j++) acc[i][j] = 0.f;

    for (int k0 = 0; k0 < KD; k0 += 16) {
        float4 wv = wvalid ? *(const float4*)(Wptr + k0) : make_float4(0.f, 0.f, 0.f, 0.f);
        if (MODE == 1) {
            const __half2* hp = (const __half2*)(ATptr + (size_t)(k0 + arow) * LL);
            __half2 h01 = hp[0], h23 = hp[1];
            float2 f01 = __half22float2(h01), f23 = __half22float2(h23);
            __syncthreads();
            *(float4*)&As[arow][acol] = make_float4(f01.x, f01.y, f23.x, f23.y);
        } else if (MODE == 2) {
            float4 av = *(const float4*)(Aptr + k0);
            float4 zv = *(const float4*)(Zptr + k0);
            __syncthreads();
            As[lk + 0][lm] = av.x * zv.x; As[lk + 1][lm] = av.y * zv.y;
            As[lk + 2][lm] = av.z * zv.z; As[lk + 3][lm] = av.w * zv.w;
        } else {
            float4 av = *(const float4*)(Aptr + k0);
            __syncthreads();
            As[lk + 0][lm] = av.x; As[lk + 1][lm] = av.y; As[lk + 2][lm] = av.z; As[lk + 3][lm] = av.w;
        }
        Ws[lk + 0][lm] = wv.x; Ws[lk + 1][lm] = wv.y; Ws[lk + 2][lm] = wv.z; Ws[lk + 3][lm] = wv.w;
        __syncthreads();
        #pragma unroll
        for (int kk = 0; kk < 16; kk++) {
            float4 a4 = *(const float4*)&As[kk][ty << 2];
            float4 w4 = *(const float4*)&Ws[kk][tx << 2];
            float ar[4] = { a4.x, a4.y, a4.z, a4.w };
            float wr[4] = { w4.x, w4.y, w4.z, w4.w };
            #pragma unroll
            for (int i = 0; i < 4; i++)
                #pragma unroll
                for (int j = 0; j < 4; j++) acc[i][j] += ar[i] * wr[j];
        }
    }

    #pragma unroll
    for (int i = 0; i < 4; i++) {
        int r = m0 + (ty << 2) + i;
        #pragma unroll
        for (int j = 0; j < 4; j++) {
            int cn = n0 + (tx << 2) + j;
            float v = acc[i][j];
            if (MODE == 0) {
                if (cn >= 192) v = v / (1.f + __expf(-v));   // silu(z)
                g_xz[(size_t)r * 384 + cn] = v;
            } else if (MODE == 1) {
                if (cn < RNK)      g_dtm[(size_t)r * RNK + cn] = v;
                else if (cn < 38)  g_BC[(size_t)r * 32 + (cn - RNK)] = v;
            } else {
                if (cn < 96) {
                    int bb = r >> 12, p = r & 4095;
                    Cout[((size_t)bb * 96 + cn) * 4096 + p] = v;
                }
            }
        }
    }
}

// ---------------- K3: depthwise causal conv + silu -> fp16 transposed ----------------
#define CONV_TL 32
__global__ void __launch_bounds__(192) conv_kernel(
    const float* __restrict__ cw, const float* __restrict__ cb)
{
    __shared__ float sbuf[DI][CONV_TL + 1];
    const int d = threadIdx.x;
    const int n = blockIdx.y;
    const int l0 = blockIdx.x * CONV_TL;
    const int b = n & 3, k = n >> 2;
    const float w0 = cw[d * 4 + 0], w1 = cw[d * 4 + 1], w2 = cw[d * 4 + 2], w3 = cw[d * 4 + 3];
    const float bias = cb[d];
    const float* xzb = g_xz + (size_t)b * LL * 384 + d;

    float x1 = (l0 - 3 >= 0) ? xzb[(size_t)pmap(l0 - 3, k) * 384] : 0.f;
    float x2 = (l0 - 2 >= 0) ? xzb[(size_t)pmap(l0 - 2, k) * 384] : 0.f;
    float x3 = (l0 - 1 >= 0) ? xzb[(size_t)pmap(l0 - 1, k) * 384] : 0.f;

    #pragma unroll 4
    for (int l = 0; l < CONV_TL; ++l) {
        float cur = xzb[(size_t)pmap(l0 + l, k) * 384];
        float v = bias + w0 * x1 + w1 * x2 + w2 * x3 + w3 * cur;
        v = v / (1.f + __expf(-v));
        sbuf[d][l] = v;
        x1 = x2; x2 = x3; x3 = cur;
    }
    __syncthreads();
    // coalesced transposed write: half2 rows
    __half* dst = g_xcT + (size_t)n * DI * LL + l0;
    for (int i = threadIdx.x; i < DI * (CONV_TL / 2); i += 192) {
        int dd = i >> 4, l2 = (i & 15) << 1;
        __half2 hv = __floats2half2_rn(sbuf[dd][l2], sbuf[dd][l2 + 1]);
        *(__half2*)(dst + (size_t)dd * LL + l2) = hv;
    }
}

// ---------------- K5: dt_proj + softplus -> fp16 delta (transposed) ----------------
#define DT_TL 256
__global__ void __launch_bounds__(128) dtproj_kernel(
    const float* __restrict__ dtw, const float* __restrict__ dtb)
{
    __shared__ float sdtm[RNK][DT_TL];
    __shared__ float sdtw[RNK][DI];
    const int tid = threadIdx.x;
    const int l0 = blockIdx.x * DT_TL;
    const int n = blockIdx.y;

    for (int i = tid; i < DT_TL * RNK; i += 128) {
        int l = i / RNK, r = i - l * RNK;
        sdtm[r][l] = g_dtm[((size_t)n * LL + l0 + l) * RNK + r];
    }
    for (int i = tid; i < DI * RNK; i += 128) {
        int dd = i / RNK, r = i - dd * RNK;
        sdtw[r][dd] = dtw[i];
    }
    __syncthreads();

    const int la = tid << 1;     // two l per thread
    __half* dst = g_dltT + (size_t)n * DI * LL + l0 + la;
    for (int d = 0; d < DI; d++) {
        float s0 = dtb[d], s1 = s0;
        #pragma unroll
        for (int r = 0; r < RNK; r++) {
            float wv = sdtw[r][d];
            s0 += sdtm[r][la] * wv;
            s1 += sdtm[r][la + 1] * wv;
        }
        s0 = (s0 > 20.f) ? s0 : __logf(1.f + __expf(s0));
        s1 = (s1 > 20.f) ? s1 : __logf(1.f + __expf(s1));
        *(__half2*)(dst + (size_t)d * LL) = __floats2half2_rn(s0, s1);
    }
}

// ---------------- chunked selective scan ----------------
// Block (c, dg, n): 128 threads = 4 warps; warp w covers d = dg*8 + {2w,2w+1}, 16 s-lanes per d.

__global__ void __launch_bounds__(128) scanA_kernel(const float* __restrict__ A_log)
{
    __shared__ float2 sdu[8][CT];
    __shared__ float sB[CT][16];
    const int tid = threadIdx.x;
    const int c = blockIdx.x, dg = blockIdx.y, n = blockIdx.z;
    const int l0 = c * CT, d0 = dg * 8;

    for (int i = tid; i < 8 * (CT / 2); i += 128) {
        int dd = i >> 5, l2 = (i & 31) << 1;
        size_t off = (size_t)n * DI * LL + (size_t)(d0 + dd) * LL + l0 + l2;
        float2 fd = __half22float2(*(const __half2*)(g_dltT + off));
        float2 fu = __half22float2(*(const __half2*)(g_xcT + off));
        sdu[dd][l2]     = make_float2(fd.x, fu.x);
        sdu[dd][l2 + 1] = make_float2(fd.y, fu.y);
    }
    for (int i = tid; i < CT * 16; i += 128) {
        int l = i >> 4, s = i & 15;
        sB[l][s] = g_BC[((size_t)n * LL + l0 + l) * 32 + s];
    }
    const int ln = tid & 31, w = tid >> 5;
    const int s = ln & 15, dloc = (w << 1) | (ln >> 4);
    const int d = d0 + dloc;
    const float cA = -expf(A_log[d * DS + s]) * 1.4426950408889634f;
    __syncthreads();

    float h = 0.f, S = 0.f;
    #pragma unroll 8
    for (int l = 0; l < CT; ++l) {
        float2 du = sdu[dloc][l];
        float a = exp2f(du.x * cA);
        h = a * h + (du.x * du.y) * sB[l][s];
        S += du.x;
    }
    size_t o = ((size_t)(n * NC + c)) * (DI * DS) + d * DS + s;
    g_H[o] = h;
    g_P[o] = exp2f(cA * S);
}

__global__ void __launch_bounds__(256) scanB_kernel()
{
    const int gid = blockIdx.x * 256 + threadIdx.x;     // < 16*3072
    const int n = gid / (DI * DS);
    const int ds = gid - n * (DI * DS);
    size_t base = (size_t)n * NC * (DI * DS) + ds;
    float h = 0.f;
    #pragma unroll 4
    for (int cc = 0; cc < NC; ++cc) {
        size_t a = base + (size_t)cc * (DI * DS);
        float Pv = g_P[a], Hv = g_H[a];
        g_H[a] = h;
        h = Pv * h + Hv;
    }
}

__global__ void __launch_bounds__(128) scanC_kernel(
    const float* __restrict__ A_log, const float* __restrict__ Dp)
{
    __shared__ float2 sdu[8][CT];
    __shared__ float sBC[CT][32];
    __shared__ float sg[CT];
    __shared__ float sv[CT][8];
    __shared__ int sp[CT];
    const int tid = threadIdx.x;
    const int c = blockIdx.x, dg = blockIdx.y, n = blockIdx.z;
    const int l0 = c * CT, d0 = dg * 8;
    const int b = n & 3, k = n >> 2;

    for (int i = tid; i < 8 * (CT / 2); i += 128) {
        int dd = i >> 5, l2 = (i & 31) << 1;
        size_t off = (size_t)n * DI * LL + (size_t)(d0 + dd) * LL + l0 + l2;
        float2 fd = __half22float2(*(const __half2*)(g_dltT + off));
        float2 fu = __half22float2(*(const __half2*)(g_xcT + off));
        sdu[dd][l2]     = make_float2(fd.x, fu.x);
        sdu[dd][l2 + 1] = make_float2(fd.y, fu.y);
    }
    for (int i = tid; i < CT * 32; i += 128) {
        int l = i >> 5, s = i & 31;
        sBC[l][s] = g_BC[((size_t)n * LL + l0 + l) * 32 + s];
    }
    if (tid < CT) {
        sp[tid] = pmap(l0 + tid, k);
        sg[tid] = g_gateT[(size_t)n * LL + l0 + tid];
    }
    const int ln = tid & 31, w = tid >> 5;
    const int s = ln & 15, dloc = (w << 1) | (ln >> 4);
    const int d = d0 + dloc;
    const float cA = -expf(A_log[d * DS + s]) * 1.4426950408889634f;
    const float Dd = Dp[d];
    __syncthreads();

    float h = g_H[((size_t)(n * NC + c)) * (DI * DS) + d * DS + s];

    #pragma unroll 4
    for (int l = 0; l < CT; ++l) {
        float2 du = sdu[dloc][l];
        float a = exp2f(du.x * cA);
        h = a * h + (du.x * du.y) * sBC[l][s];
        float y = h * sBC[l][16 + s];
        y += __shfl_xor_sync(0xffffffffu, y, 1);
        y += __shfl_xor_sync(0xffffffffu, y, 2);
        y += __shfl_xor_sync(0xffffffffu, y, 4);
        y += __shfl_xor_sync(0xffffffffu, y, 8);
        if (s == 0)
            sv[l][dloc] = (y + du.y * Dd) * sg[l];
    }
    __syncthreads();

    // coalesced batched atomic scatter: 8 lanes cover 32B-contiguous [p][d0..d0+7]
    float* ycb = g_ycomb + (size_t)b * LL * DI + d0;
    #pragma unroll
    for (int j = 0; j < 4; j++) {
        int i = tid + j * 128;          // 0..511
        int dd = i & 7, l = i >> 3;
        atomicAdd(ycb + (size_t)sp[l] * DI + dd, sv[l][dd]);
    }
}

// ---------------- launch ----------------
extern "C" void kernel_launch(void* const* d_in, const int* in_sizes, int n_in,
                              void* d_out, int out_size)
{
    const float* x         = (const float*)d_in[0];
    const float* norm_g    = (const float*)d_in[1];
    const float* norm_b    = (const float*)d_in[2];
    const float* gate_w1   = (const float*)d_in[3];
    const float* gate_b1   = (const float*)d_in[4];
    const float* gate_w2   = (const float*)d_in[5];
    const float* gate_b2   = (const float*)d_in[6];
    const float* in_proj_w = (const float*)d_in[7];
    const float* conv_w    = (const float*)d_in[8];
    const float* conv_b    = (const float*)d_in[9];
    const float* x_proj_w  = (const float*)d_in[10];
    const float* dt_proj_w = (const float*)d_in[11];
    const float* dt_proj_b = (const float*)d_in[12];
    const float* A_log     = (const float*)d_in[13];
    const float* Dvec      = (const float*)d_in[14];
    const float* out_proj_w= (const float*)d_in[15];
    float* out = (float*)d_out;

    norm_gate_kernel<<<512, 128>>>(x, norm_g, norm_b, gate_w1, gate_b1, gate_w2, gate_b2);
    gemm_kernel<96, 0><<<dim3(256, 6), 256>>>(in_proj_w, nullptr, 384);
    conv_kernel<<<dim3(LL / CONV_TL, NDIR), 192>>>(conv_w, conv_b);
    gemm_kernel<192, 1><<<dim3(1024, 1), 256>>>(x_proj_w, nullptr, 38);
    dtproj_kernel<<<dim3(LL / DT_TL, NDIR), 128>>>(dt_proj_w, dt_proj_b);
    scanA_kernel<<<dim3(NC, 24, NDIR), 128>>>(A_log);
    scanB_kernel<<<(NDIR * DI * DS) / 256, 256>>>();
    scanC_kernel<<<dim3(NC, 24, NDIR), 128>>>(A_log, Dvec);
    gemm_kernel<192, 2><<<dim3(256, 2), 256>>>(out_proj_w, out, 96);
}

// round 6
// speedup vs baseline: 9.7264x; 1.4337x over previous
#include <cuda_runtime.h>
#include <cuda_fp16.h>
#include <math.h>

// ---------------- problem constants ----------------
#define BB    4
#define CDIM  96
#define LL    4096      // 64*64
#define DI    192
#define DS    16
#define RNK   6
#define NDIR  16        // 4 directions * BB
#define CT    64        // chunk length
#define NC    64        // number of chunks

// ---------------- scratch (device globals; no allocation) ----------------
__device__ float  g_xn[BB * LL * CDIM];             // [b][p][c]
__device__ float  g_gateT[(size_t)NDIR * LL];       // [n][l]
__device__ float  g_xz[(size_t)BB * LL * 384];      // [b][p][e] (e>=192 = silu(z))
__device__ __half g_xcT[(size_t)NDIR * DI * LL];    // [n][d][l]  fp16
__device__ __half g_dltT[(size_t)NDIR * DI * LL];   // [n][d][l]  fp16
__device__ float  g_dtm[(size_t)NDIR * LL * RNK];   // [n][l][r]
__device__ float  g_BC[(size_t)NDIR * LL * 32];     // [n][l][B0..15,C0..15]
__device__ float  g_ycomb[(size_t)BB * LL * DI];    // [b][p][d]
__device__ float  g_H[(size_t)NDIR * NC * DI * DS]; // [n][c][d][s]
__device__ float  g_P[(size_t)NDIR * NC * DI * DS]; // [n][c][d][s]
__device__ __half g_Wh1[48 * 192];                  // x_proj_w fp16, padded to 48 rows
__device__ __half g_Wh2[96 * 192];                  // out_proj_w fp16

__device__ __forceinline__ int pmap(int l, int k) {
    int lr = (k & 2) ? (LL - 1 - l) : l;
    return (k & 1) ? (((lr & 63) << 6) | (lr >> 6)) : lr;
}

__device__ __forceinline__ void mma16816(float* d, const unsigned* a, const unsigned* b) {
    asm volatile("mma.sync.aligned.m16n8k16.row.col.f32.f16.f16.f32 "
        "{%0,%1,%2,%3}, {%4,%5,%6,%7}, {%8,%9}, {%0,%1,%2,%3};"
        : "+f"(d[0]), "+f"(d[1]), "+f"(d[2]), "+f"(d[3])
        : "r"(a[0]), "r"(a[1]), "r"(a[2]), "r"(a[3]), "r"(b[0]), "r"(b[1]));
}
__device__ __forceinline__ unsigned pack2(__half lo, __half hi) {
    __half2 h = __halves2half2(lo, hi);
    return *(unsigned*)&h;
}

// ---------------- prep: fp16 weight copies ----------------
__global__ void __launch_bounds__(256) prep_weights(
    const float* __restrict__ xw, const float* __restrict__ ow)
{
    int i = blockIdx.x * 256 + threadIdx.x;
    if (i < 48 * 192) {
        int r = i / 192, c = i - r * 192;
        g_Wh1[i] = __float2half(r < 38 ? xw[r * 192 + c] : 0.f);
    }
    if (i < 96 * 192) g_Wh2[i] = __float2half(ow[i]);
}

// ---------------- K1: layernorm + gate MLP (+ zero ycomb, scatter gateT) ----------------
__global__ void __launch_bounds__(128) norm_gate_kernel(
    const float* __restrict__ x, const float* __restrict__ ng, const float* __restrict__ nb,
    const float* __restrict__ w1, const float* __restrict__ b1,
    const float* __restrict__ w2, const float* __restrict__ b2)
{
    __shared__ float xs_s[CDIM][33];
    __shared__ float w1_s[24 * 96];
    const int tid = threadIdx.x;
    const int P0 = blockIdx.x * 32;
    const int b = P0 >> 12, p0 = P0 & 4095;

    {
        size_t base = (size_t)blockIdx.x * 6144;
        for (int i = tid; i < 6144; i += 128) g_ycomb[base + i] = 0.f;
    }
    for (int i = tid; i < 96 * 32; i += 128) {
        int c = i >> 5, pi = i & 31;
        xs_s[c][pi] = x[((size_t)b * 96 + c) * 4096 + p0 + pi];
    }
    for (int i = tid; i < 24 * 96; i += 128) w1_s[i] = w1[i];
    __syncthreads();

    if (tid < 32) {
        const int lane = tid;
        float mu = 0.f;
        #pragma unroll
        for (int c = 0; c < 96; c++) mu += xs_s[c][lane];
        mu *= (1.f / 96.f);
        float var = 0.f;
        #pragma unroll
        for (int c = 0; c < 96; c++) { float dv = xs_s[c][lane] - mu; var += dv * dv; }
        var *= (1.f / 96.f);
        const float inv = rsqrtf(var + 1e-5f);
        #pragma unroll
        for (int c = 0; c < 96; c++)
            xs_s[c][lane] = (xs_s[c][lane] - mu) * inv * ng[c] + nb[c];

        float hbuf[24];
        #pragma unroll 4
        for (int jj = 0; jj < 24; jj++) {
            float s = b1[jj];
            for (int c = 0; c < 96; c++) s += xs_s[c][lane] * w1_s[jj * 96 + c];
            hbuf[jj] = tanhf(s);
        }
        float lg[4];
        #pragma unroll
        for (int q = 0; q < 4; q++) {
            float s = b2[q];
            #pragma unroll
            for (int jj = 0; jj < 24; jj++) s += hbuf[jj] * w2[q * 24 + jj];
            lg[q] = s;
        }
        float m = fmaxf(fmaxf(lg[0], lg[1]), fmaxf(lg[2], lg[3]));
        float e[4], se = 0.f;
        #pragma unroll
        for (int q = 0; q < 4; q++) { e[q] = __expf(lg[q] - m); se += e[q]; }
        float rs = 1.f / se;
        const int p = p0 + lane;
        #pragma unroll
        for (int q = 0; q < 4; q++) {
            int l = pmap(p, q);
            g_gateT[(size_t)(q * 4 + b) * LL + l] = e[q] * rs;
        }
    }
    __syncthreads();
    for (int i = tid; i < 32 * 96; i += 128) {
        int pi = i / 96, c = i % 96;
        g_xn[(size_t)(b * 4096 + p0 + pi) * 96 + c] = xs_s[c][pi];
    }
}

// ---------------- in_proj fp32 GEMM (kept fp32 for precision) ----------------
__global__ void __launch_bounds__(256) inproj_kernel(const float* __restrict__ W)
{
    __shared__ float As[16][64];
    __shared__ float Ws[16][64];
    const int tid = threadIdx.x;
    const int tx = tid & 15, ty = tid >> 4;
    const int m0 = blockIdx.x * 64;
    const int n0 = blockIdx.y * 64;

    const int lm = tid >> 2;
    const int lk = (tid & 3) * 4;
    const float* Aptr = g_xn + (size_t)(m0 + lm) * 96 + lk;
    const float* Wptr = W + (size_t)(n0 + lm) * 96 + lk;

    float acc[4][4];
    #pragma unroll
    for (int i = 0; i < 4; i++)
        #pragma unroll
        for (int j = 0; j < 4; j++) acc[i][j] = 0.f;

    for (int k0 = 0; k0 < 96; k0 += 16) {
        float4 av = *(const float4*)(Aptr + k0);
        float4 wv = *(const float4*)(Wptr + k0);
        __syncthreads();
        As[lk + 0][lm] = av.x; As[lk + 1][lm] = av.y; As[lk + 2][lm] = av.z; As[lk + 3][lm] = av.w;
        Ws[lk + 0][lm] = wv.x; Ws[lk + 1][lm] = wv.y; Ws[lk + 2][lm] = wv.z; Ws[lk + 3][lm] = wv.w;
        __syncthreads();
        #pragma unroll
        for (int kk = 0; kk < 16; kk++) {
            float4 a4 = *(const float4*)&As[kk][ty << 2];
            float4 w4 = *(const float4*)&Ws[kk][tx << 2];
            float ar[4] = { a4.x, a4.y, a4.z, a4.w };
            float wr[4] = { w4.x, w4.y, w4.z, w4.w };
            #pragma unroll
            for (int i = 0; i < 4; i++)
                #pragma unroll
                for (int j = 0; j < 4; j++) acc[i][j] += ar[i] * wr[j];
        }
    }
    #pragma unroll
    for (int i = 0; i < 4; i++) {
        int r = m0 + (ty << 2) + i;
        #pragma unroll
        for (int j = 0; j < 4; j++) {
            int cn = n0 + (tx << 2) + j;
            float v = acc[i][j];
            if (cn >= 192) v = v / (1.f + __expf(-v));   // silu(z)
            g_xz[(size_t)r * 384 + cn] = v;
        }
    }
}

// ---------------- x_proj via tensor cores ----------------
// D[48 nbar][64 tok] per block; A-op = W (row-major [48][192]), B-op = xcT from global.
__global__ void __launch_bounds__(128) xproj_mma()
{
    __shared__ __half sW[48 * 200];
    const int tid = threadIdx.x;
    const int w = tid >> 5, lane = tid & 31;
    const int m0 = blockIdx.x * 64;
    const int nd = m0 >> 12, l0 = m0 & 4095;

    for (int i = tid; i < 48 * 192; i += 128) {
        int r = i / 192, c = i - r * 192;
        sW[r * 200 + c] = g_Wh1[i];
    }
    __syncthreads();

    const __half* X = g_xcT + (size_t)nd * DI * LL;
    const int qr = lane >> 2, qc = (lane & 3) << 1;
    const int tB = l0 + w * 16 + qr;

    float acc[3][2][4];
    #pragma unroll
    for (int g = 0; g < 3; g++)
        #pragma unroll
        for (int t = 0; t < 2; t++)
            #pragma unroll
            for (int q = 0; q < 4; q++) acc[g][t][q] = 0.f;

    #pragma unroll 2
    for (int ks = 0; ks < 12; ks++) {
        const int k = ks * 16 + qc;
        unsigned a[3][4];
        #pragma unroll
        for (int g = 0; g < 3; g++) {
            int r = g * 16 + qr;
            a[g][0] = *(const unsigned*)&sW[r * 200 + k];
            a[g][1] = *(const unsigned*)&sW[(r + 8) * 200 + k];
            a[g][2] = *(const unsigned*)&sW[r * 200 + k + 8];
            a[g][3] = *(const unsigned*)&sW[(r + 8) * 200 + k + 8];
        }
        unsigned bf[2][2];
        #pragma unroll
        for (int tg = 0; tg < 2; tg++) {
            const __half* xp = X + (size_t)k * LL + tB + tg * 8;
            bf[tg][0] = pack2(xp[0], xp[LL]);
            bf[tg][1] = pack2(xp[8 * LL], xp[9 * LL]);
        }
        #pragma unroll
        for (int g = 0; g < 3; g++)
            #pragma unroll
            for (int tg = 0; tg < 2; tg++)
                mma16816(acc[g][tg], a[g], bf[tg]);
    }

    #pragma unroll
    for (int g = 0; g < 3; g++) {
        #pragma unroll
        for (int tg = 0; tg < 2; tg++) {
            int T = m0 + w * 16 + tg * 8 + qc;    // token (D col)
            #pragma unroll
            for (int q = 0; q < 4; q++) {
                int nb = g * 16 + qr + ((q >= 2) ? 8 : 0);
                int Tt = T + (q & 1);
                float v = acc[g][tg][q];
                if (nb < RNK)        g_dtm[(size_t)Tt * RNK + nb] = v;
                else if (nb < 38)    g_BC[(size_t)Tt * 32 + (nb - RNK)] = v;
            }
        }
    }
}

// ---------------- out_proj via tensor cores ----------------
// A-op = (ycomb .* silu(z)) fp16 staged in smem; B-op = W2 from global.
__global__ void __launch_bounds__(128) outproj_mma(float* __restrict__ out)
{
    __shared__ __half sA[64 * 200];
    const int tid = threadIdx.x;
    const int w = tid >> 5, lane = tid & 31;
    const int m0 = blockIdx.x * 64;
    const int b = m0 >> 12, p0 = m0 & 4095;

    for (int i = tid; i < 64 * 48; i += 128) {
        int m = i / 48, kq = (i - m * 48) * 4;
        float4 yv = *(const float4*)&g_ycomb[(size_t)(m0 + m) * 192 + kq];
        float4 zv = *(const float4*)&g_xz[(size_t)(m0 + m) * 384 + 192 + kq];
        *(__half2*)&sA[m * 200 + kq]     = __floats2half2_rn(yv.x * zv.x, yv.y * zv.y);
        *(__half2*)&sA[m * 200 + kq + 2] = __floats2half2_rn(yv.z * zv.z, yv.w * zv.w);
    }
    __syncthreads();

    const int qr = lane >> 2, qc = (lane & 3) << 1;
    const int rA = w * 16 + qr;

    float acc[12][4];
    #pragma unroll
    for (int g = 0; g < 12; g++)
        #pragma unroll
        for (int q = 0; q < 4; q++) acc[g][q] = 0.f;

    for (int ks = 0; ks < 12; ks++) {
        const int k = ks * 16 + qc;
        unsigned a[4];
        a[0] = *(const unsigned*)&sA[rA * 200 + k];
        a[1] = *(const unsigned*)&sA[(rA + 8) * 200 + k];
        a[2] = *(const unsigned*)&sA[rA * 200 + k + 8];
        a[3] = *(const unsigned*)&sA[(rA + 8) * 200 + k + 8];
        #pragma unroll
        for (int g = 0; g < 12; g++) {
            int n = g * 8 + qr;
            unsigned bf[2];
            bf[0] = *(const unsigned*)&g_Wh2[n * 192 + k];
            bf[1] = *(const unsigned*)&g_Wh2[n * 192 + k + 8];
            mma16816(acc[g], a, bf);
        }
    }

    #pragma unroll
    for (int g = 0; g < 12; g++) {
        int nc = g * 8 + qc;
        int t = p0 + w * 16 + qr;
        out[((size_t)b * 96 + nc)     * 4096 + t]     = acc[g][0];
        out[((size_t)b * 96 + nc + 1) * 4096 + t]     = acc[g][1];
        out[((size_t)b * 96 + nc)     * 4096 + t + 8] = acc[g][2];
        out[((size_t)b * 96 + nc + 1) * 4096 + t + 8] = acc[g][3];
    }
}

// ---------------- K3: depthwise causal conv + silu -> fp16 transposed ----------------
#define CONV_TL 32
__global__ void __launch_bounds__(192) conv_kernel(
    const float* __restrict__ cw, const float* __restrict__ cb)
{
    __shared__ float sbuf[DI][CONV_TL + 1];
    const int d = threadIdx.x;
    const int n = blockIdx.y;
    const int l0 = blockIdx.x * CONV_TL;
    const int b = n & 3, k = n >> 2;
    const float w0 = cw[d * 4 + 0], w1 = cw[d * 4 + 1], w2 = cw[d * 4 + 2], w3 = cw[d * 4 + 3];
    const float bias = cb[d];
    const float* xzb = g_xz + (size_t)b * LL * 384 + d;

    float x1 = (l0 - 3 >= 0) ? xzb[(size_t)pmap(l0 - 3, k) * 384] : 0.f;
    float x2 = (l0 - 2 >= 0) ? xzb[(size_t)pmap(l0 - 2, k) * 384] : 0.f;
    float x3 = (l0 - 1 >= 0) ? xzb[(size_t)pmap(l0 - 1, k) * 384] : 0.f;

    #pragma unroll 4
    for (int l = 0; l < CONV_TL; ++l) {
        float cur = xzb[(size_t)pmap(l0 + l, k) * 384];
        float v = bias + w0 * x1 + w1 * x2 + w2 * x3 + w3 * cur;
        v = v / (1.f + __expf(-v));
        sbuf[d][l] = v;
        x1 = x2; x2 = x3; x3 = cur;
    }
    __syncthreads();
    __half* dst = g_xcT + (size_t)n * DI * LL + l0;
    for (int i = threadIdx.x; i < DI * (CONV_TL / 2); i += 192) {
        int dd = i >> 4, l2 = (i & 15) << 1;
        __half2 hv = __floats2half2_rn(sbuf[dd][l2], sbuf[dd][l2 + 1]);
        *(__half2*)(dst + (size_t)dd * LL + l2) = hv;
    }
}

// ---------------- K5: dt_proj + softplus -> fp16 delta (transposed) ----------------
#define DT_TL 256
__global__ void __launch_bounds__(128) dtproj_kernel(
    const float* __restrict__ dtw, const float* __restrict__ dtb)
{
    __shared__ float sdtm[RNK][DT_TL];
    __shared__ float sdtw[RNK][DI];
    const int tid = threadIdx.x;
    const int l0 = blockIdx.x * DT_TL;
    const int n = blockIdx.y;

    for (int i = tid; i < DT_TL * RNK; i += 128) {
        int l = i / RNK, r = i - l * RNK;
        sdtm[r][l] = g_dtm[((size_t)n * LL + l0 + l) * RNK + r];
    }
    for (int i = tid; i < DI * RNK; i += 128) {
        int dd = i / RNK, r = i - dd * RNK;
        sdtw[r][dd] = dtw[i];
    }
    __syncthreads();

    const int la = tid << 1;
    __half* dst = g_dltT + (size_t)n * DI * LL + l0 + la;
    for (int d = 0; d < DI; d++) {
        float s0 = dtb[d], s1 = s0;
        #pragma unroll
        for (int r = 0; r < RNK; r++) {
            float wv = sdtw[r][d];
            s0 += sdtm[r][la] * wv;
            s1 += sdtm[r][la + 1] * wv;
        }
        s0 = (s0 > 20.f) ? s0 : __logf(1.f + __expf(s0));
        s1 = (s1 > 20.f) ? s1 : __logf(1.f + __expf(s1));
        *(__half2*)(dst + (size_t)d * LL) = __floats2half2_rn(s0, s1);
    }
}

// ---------------- chunked selective scan (2 states/lane, 16 d/block) ----------------
__global__ void __launch_bounds__(128) scanA_kernel(const float* __restrict__ A_log)
{
    __shared__ float2 sdu[16][CT + 2];
    __shared__ float2 sB[CT][8];
    const int tid = threadIdx.x;
    const int c = blockIdx.x, dg = blockIdx.y, n = blockIdx.z;
    const int l0 = c * CT, d0 = dg * 16;

    for (int i = tid; i < 16 * (CT / 2); i += 128) {
        int dd = i >> 5, l2 = (i & 31) << 1;
        size_t off = (size_t)n * DI * LL + (size_t)(d0 + dd) * LL + l0 + l2;
        float2 fd = __half22float2(*(const __half2*)(g_dltT + off));
        float2 fu = __half22float2(*(const __half2*)(g_xcT + off));
        sdu[dd][l2]     = make_float2(fd.x, fu.x);
        sdu[dd][l2 + 1] = make_float2(fd.y, fu.y);
    }
    for (int i = tid; i < CT * 8; i += 128) {
        int l = i >> 3, j = i & 7;
        sB[l][j] = *(const float2*)&g_BC[((size_t)n * LL + l0 + l) * 32 + 2 * j];
    }
    const int lane = tid & 31, w = tid >> 5;
    const int j = lane & 7, dloc = (w << 2) | (lane >> 3);
    const int d = d0 + dloc;
    float2 al = *(const float2*)&A_log[d * DS + 2 * j];
    const float cA0 = -expf(al.x) * 1.4426950408889634f;
    const float cA1 = -expf(al.y) * 1.4426950408889634f;
    __syncthreads();

    float h0 = 0.f, h1 = 0.f, S = 0.f;
    #pragma unroll 4
    for (int l = 0; l < CT; ++l) {
        float2 du = sdu[dloc][l];
        float2 Bv = sB[l][j];
        float a0 = exp2f(du.x * cA0);
        float a1 = exp2f(du.x * cA1);
        float du2 = du.x * du.y;
        h0 = a0 * h0 + du2 * Bv.x;
        h1 = a1 * h1 + du2 * Bv.y;
        S += du.x;
    }
    size_t o = ((size_t)(n * NC + c)) * (DI * DS) + d * DS + 2 * j;
    *(float2*)&g_H[o] = make_float2(h0, h1);
    *(float2*)&g_P[o] = make_float2(exp2f(cA0 * S), exp2f(cA1 * S));
}

__global__ void __launch_bounds__(256) scanB_kernel()
{
    const int gid = blockIdx.x * 256 + threadIdx.x;
    const int n = gid / (DI * DS);
    const int ds = gid - n * (DI * DS);
    size_t base = (size_t)n * NC * (DI * DS) + ds;
    float h = 0.f;
    #pragma unroll 4
    for (int cc = 0; cc < NC; ++cc) {
        size_t a = base + (size_t)cc * (DI * DS);
        float Pv = g_P[a], Hv = g_H[a];
        g_H[a] = h;
        h = Pv * h + Hv;
    }
}

__global__ void __launch_bounds__(128) scanC_kernel(
    const float* __restrict__ A_log, const float* __restrict__ Dp)
{
    __shared__ float2 sdu[16][CT + 2];
    __shared__ float2 sB[CT][8];
    __shared__ float2 sC[CT][8];
    __shared__ float sg[CT];
    __shared__ float sv[CT][16];
    __shared__ int sp[CT];
    const int tid = threadIdx.x;
    const int c = blockIdx.x, dg = blockIdx.y, n = blockIdx.z;
    const int l0 = c * CT, d0 = dg * 16;
    const int b = n & 3, k = n >> 2;

    for (int i = tid; i < 16 * (CT / 2); i += 128) {
        int dd = i >> 5, l2 = (i & 31) << 1;
        size_t off = (size_t)n * DI * LL + (size_t)(d0 + dd) * LL + l0 + l2;
        float2 fd = __half22float2(*(const __half2*)(g_dltT + off));
        float2 fu = __half22float2(*(const __half2*)(g_xcT + off));
        sdu[dd][l2]     = make_float2(fd.x, fu.x);
        sdu[dd][l2 + 1] = make_float2(fd.y, fu.y);
    }
    for (int i = tid; i < CT * 8; i += 128) {
        int l = i >> 3, j = i & 7;
        const float* bc = &g_BC[((size_t)n * LL + l0 + l) * 32];
        sB[l][j] = *(const float2*)(bc + 2 * j);
        sC[l][j] = *(const float2*)(bc + 16 + 2 * j);
    }
    if (tid < CT) {
        sp[tid] = pmap(l0 + tid, k);
        sg[tid] = g_gateT[(size_t)n * LL + l0 + tid];
    }
    const int lane = tid & 31, w = tid >> 5;
    const int j = lane & 7, dloc = (w << 2) | (lane >> 3);
    const int d = d0 + dloc;
    float2 al = *(const float2*)&A_log[d * DS + 2 * j];
    const float cA0 = -expf(al.x) * 1.4426950408889634f;
    const float cA1 = -expf(al.y) * 1.4426950408889634f;
    const float Dd = Dp[d];
    __syncthreads();

    float2 hv = *(const float2*)&g_H[((size_t)(n * NC + c)) * (DI * DS) + d * DS + 2 * j];
    float h0 = hv.x, h1 = hv.y;

    #pragma unroll 4
    for (int l = 0; l < CT; ++l) {
        float2 du = sdu[dloc][l];
        float2 Bv = sB[l][j];
        float2 Cv = sC[l][j];
        float a0 = exp2f(du.x * cA0);
        float a1 = exp2f(du.x * cA1);
        float du2 = du.x * du.y;
        h0 = a0 * h0 + du2 * Bv.x;
        h1 = a1 * h1 + du2 * Bv.y;
        float y = h0 * Cv.x + h1 * Cv.y;
        y += __shfl_xor_sync(0xffffffffu, y, 1);
        y += __shfl_xor_sync(0xffffffffu, y, 2);
        y += __shfl_xor_sync(0xffffffffu, y, 4);
        if (j == 0)
            sv[l][dloc] = (y + du.y * Dd) * sg[l];
    }
    __syncthreads();

    float* ycb = g_ycomb + (size_t)b * LL * DI + d0;
    #pragma unroll
    for (int jj = 0; jj < 8; jj++) {
        int i = tid + jj * 128;          // 0..1023
        int dd = i & 15, l = i >> 4;
        atomicAdd(ycb + (size_t)sp[l] * DI + dd, sv[l][dd]);
    }
}

// ---------------- launch ----------------
extern "C" void kernel_launch(void* const* d_in, const int* in_sizes, int n_in,
                              void* d_out, int out_size)
{
    const float* x         = (const float*)d_in[0];
    const float* norm_g    = (const float*)d_in[1];
    const float* norm_b    = (const float*)d_in[2];
    const float* gate_w1   = (const float*)d_in[3];
    const float* gate_b1   = (const float*)d_in[4];
    const float* gate_w2   = (const float*)d_in[5];
    const float* gate_b2   = (const float*)d_in[6];
    const float* in_proj_w = (const float*)d_in[7];
    const float* conv_w    = (const float*)d_in[8];
    const float* conv_b    = (const float*)d_in[9];
    const float* x_proj_w  = (const float*)d_in[10];
    const float* dt_proj_w = (const float*)d_in[11];
    const float* dt_proj_b = (const float*)d_in[12];
    const float* A_log     = (const float*)d_in[13];
    const float* Dvec      = (const float*)d_in[14];
    const float* out_proj_w= (const float*)d_in[15];
    float* out = (float*)d_out;

    prep_weights<<<72, 256>>>(x_proj_w, out_proj_w);
    norm_gate_kernel<<<512, 128>>>(x, norm_g, norm_b, gate_w1, gate_b1, gate_w2, gate_b2);
    inproj_kernel<<<dim3(256, 6), 256>>>(in_proj_w);
    conv_kernel<<<dim3(LL / CONV_TL, NDIR), 192>>>(conv_w, conv_b);
    xproj_mma<<<1024, 128>>>();
    dtproj_kernel<<<dim3(LL / DT_TL, NDIR), 128>>>(dt_proj_w, dt_proj_b);
    scanA_kernel<<<dim3(NC, 12, NDIR), 128>>>(A_log);
    scanB_kernel<<<(NDIR * DI * DS) / 256, 256>>>();
    scanC_kernel<<<dim3(NC, 12, NDIR), 128>>>(A_log, Dvec);
    outproj_mma<<<256, 128>>>(out);
}

// round 7
// speedup vs baseline: 10.1758x; 1.0462x over previous
#include <cuda_runtime.h>
#include <cuda_fp16.h>
#include <math.h>

// ---------------- problem constants ----------------
#define BB    4
#define CDIM  96
#define LL    4096      // 64*64
#define DI    192
#define DS    16
#define RNK   6
#define NDIR  16        // 4 directions * BB
#define CT    64        // chunk length
#define NC    64        // number of chunks

// ---------------- scratch (device globals; no allocation) ----------------
__device__ float  g_xn[BB * LL * CDIM];             // [b][p][c]
__device__ float  g_gateT[(size_t)NDIR * LL];       // [n][l]
__device__ __half g_xsh[(size_t)BB * LL * DI];      // [b][p][d]  xs fp16
__device__ float  g_zs[(size_t)BB * LL * DI];       // [b][p][d]  silu(z) fp32
__device__ __half g_xcT[(size_t)NDIR * DI * LL];    // [n][d][l]  fp16
__device__ __half g_dltT[(size_t)NDIR * DI * LL];   // [n][d][l]  fp16
__device__ float  g_dtm[(size_t)NDIR * LL * RNK];   // [n][l][r]
__device__ float  g_BC[(size_t)NDIR * LL * 32];     // [n][l][B0..15,C0..15]
__device__ float  g_ycomb[(size_t)BB * LL * DI];    // [b][p][d]
__device__ float  g_H[(size_t)NDIR * NC * DI * DS]; // [n][c][d][s]
__device__ float  g_P[(size_t)NDIR * NC * DI * DS]; // [n][c][d][s]
__device__ __half g_Wh1[48 * 192];                  // x_proj_w fp16 (padded 48 rows)
__device__ __half g_Wh2[96 * 192];                  // out_proj_w fp16
__device__ __half g_Whin[384 * 96];                 // in_proj_w fp16

__device__ __forceinline__ int pmap(int l, int k) {
    int lr = (k & 2) ? (LL - 1 - l) : l;
    return (k & 1) ? (((lr & 63) << 6) | (lr >> 6)) : lr;
}

__device__ __forceinline__ void mma16816(float* d, const unsigned* a, const unsigned* b) {
    asm volatile("mma.sync.aligned.m16n8k16.row.col.f32.f16.f16.f32 "
        "{%0,%1,%2,%3}, {%4,%5,%6,%7}, {%8,%9}, {%0,%1,%2,%3};"
        : "+f"(d[0]), "+f"(d[1]), "+f"(d[2]), "+f"(d[3])
        : "r"(a[0]), "r"(a[1]), "r"(a[2]), "r"(a[3]), "r"(b[0]), "r"(b[1]));
}
__device__ __forceinline__ unsigned pack2(__half lo, __half hi) {
    __half2 h = __halves2half2(lo, hi);
    return *(unsigned*)&h;
}
__device__ __forceinline__ float silu(float v) { return v / (1.f + __expf(-v)); }

// ---------------- prep: fp16 weight copies ----------------
__global__ void __launch_bounds__(256) prep_weights(
    const float* __restrict__ xw, const float* __restrict__ ow, const float* __restrict__ iw)
{
    int i = blockIdx.x * 256 + threadIdx.x;
    if (i < 48 * 192) {
        int r = i / 192, c = i - r * 192;
        g_Wh1[i] = __float2half(r < 38 ? xw[r * 192 + c] : 0.f);
    }
    if (i < 96 * 192) g_Wh2[i] = __float2half(ow[i]);
    if (i < 384 * 96) g_Whin[i] = __float2half(iw[i]);
}

// ---------------- K1: layernorm + gate MLP (+ zero ycomb, scatter gateT) ----------------
__global__ void __launch_bounds__(128) norm_gate_kernel(
    const float* __restrict__ x, const float* __restrict__ ng, const float* __restrict__ nb,
    const float* __restrict__ w1, const float* __restrict__ b1,
    const float* __restrict__ w2, const float* __restrict__ b2)
{
    __shared__ float xs_s[CDIM][33];
    __shared__ float w1_s[24 * 96];
    const int tid = threadIdx.x;
    const int P0 = blockIdx.x * 32;
    const int b = P0 >> 12, p0 = P0 & 4095;

    {
        size_t base = (size_t)blockIdx.x * 6144;
        for (int i = tid; i < 6144; i += 128) g_ycomb[base + i] = 0.f;
    }
    for (int i = tid; i < 96 * 32; i += 128) {
        int c = i >> 5, pi = i & 31;
        xs_s[c][pi] = x[((size_t)b * 96 + c) * 4096 + p0 + pi];
    }
    for (int i = tid; i < 24 * 96; i += 128) w1_s[i] = w1[i];
    __syncthreads();

    if (tid < 32) {
        const int lane = tid;
        float mu = 0.f;
        #pragma unroll
        for (int c = 0; c < 96; c++) mu += xs_s[c][lane];
        mu *= (1.f / 96.f);
        float var = 0.f;
        #pragma unroll
        for (int c = 0; c < 96; c++) { float dv = xs_s[c][lane] - mu; var += dv * dv; }
        var *= (1.f / 96.f);
        const float inv = rsqrtf(var + 1e-5f);
        #pragma unroll
        for (int c = 0; c < 96; c++)
            xs_s[c][lane] = (xs_s[c][lane] - mu) * inv * ng[c] + nb[c];

        float hbuf[24];
        #pragma unroll 4
        for (int jj = 0; jj < 24; jj++) {
            float s = b1[jj];
            for (int c = 0; c < 96; c++) s += xs_s[c][lane] * w1_s[jj * 96 + c];
            hbuf[jj] = tanhf(s);
        }
        float lg[4];
        #pragma unroll
        for (int q = 0; q < 4; q++) {
            float s = b2[q];
            #pragma unroll
            for (int jj = 0; jj < 24; jj++) s += hbuf[jj] * w2[q * 24 + jj];
            lg[q] = s;
        }
        float m = fmaxf(fmaxf(lg[0], lg[1]), fmaxf(lg[2], lg[3]));
        float e[4], se = 0.f;
        #pragma unroll
        for (int q = 0; q < 4; q++) { e[q] = __expf(lg[q] - m); se += e[q]; }
        float rs = 1.f / se;
        const int p = p0 + lane;
        #pragma unroll
        for (int q = 0; q < 4; q++) {
            int l = pmap(p, q);
            g_gateT[(size_t)(q * 4 + b) * LL + l] = e[q] * rs;
        }
    }
    __syncthreads();
    for (int i = tid; i < 32 * 96; i += 128) {
        int pi = i / 96, c = i % 96;
        g_xn[(size_t)(b * 4096 + p0 + pi) * 96 + c] = xs_s[c][pi];
    }
}

// ---------------- in_proj via tensor cores ----------------
// Block: 64 tokens x 384 outputs. 8 warps: warp w -> tokens (w&3)*16, N-half (w>>2)*192.
__global__ void __launch_bounds__(256) inproj_mma()
{
    __shared__ __half sA[64][104];
    const int tid = threadIdx.x;
    const int w = tid >> 5, lane = tid & 31;
    const int m0 = blockIdx.x * 64;

    for (int i = tid; i < 64 * 24; i += 256) {
        int m = i / 24, kq = (i - m * 24) * 4;
        float4 v = *(const float4*)&g_xn[(size_t)(m0 + m) * 96 + kq];
        *(__half2*)&sA[m][kq]     = __floats2half2_rn(v.x, v.y);
        *(__half2*)&sA[m][kq + 2] = __floats2half2_rn(v.z, v.w);
    }
    __syncthreads();

    const int qr = lane >> 2, qc = (lane & 3) << 1;
    const int wt = w & 3, nh = (w >> 2) * 192;
    const int rA = wt * 16 + qr;

    float acc[24][4];
    #pragma unroll
    for (int g = 0; g < 24; g++)
        #pragma unroll
        for (int q = 0; q < 4; q++) acc[g][q] = 0.f;

    #pragma unroll
    for (int ks = 0; ks < 6; ks++) {
        const int k = ks * 16 + qc;
        unsigned a[4];
        a[0] = *(const unsigned*)&sA[rA][k];
        a[1] = *(const unsigned*)&sA[rA + 8][k];
        a[2] = *(const unsigned*)&sA[rA][k + 8];
        a[3] = *(const unsigned*)&sA[rA + 8][k + 8];
        #pragma unroll
        for (int g = 0; g < 24; g++) {
            int n = nh + g * 8 + qr;
            unsigned bf[2];
            bf[0] = *(const unsigned*)&g_Whin[n * 96 + k];
            bf[1] = *(const unsigned*)&g_Whin[n * 96 + k + 8];
            mma16816(acc[g], a, bf);
        }
    }

    const int t0 = m0 + wt * 16 + qr;
    #pragma unroll
    for (int g = 0; g < 24; g++) {
        int cn = nh + g * 8 + qc;
        if (nh == 0) {   // xs half -> fp16
            *(__half2*)&g_xsh[(size_t)t0 * DI + cn]       = __floats2half2_rn(acc[g][0], acc[g][1]);
            *(__half2*)&g_xsh[(size_t)(t0 + 8) * DI + cn] = __floats2half2_rn(acc[g][2], acc[g][3]);
        } else {         // z half -> silu fp32
            int zc = cn - 192;
            *(float2*)&g_zs[(size_t)t0 * DI + zc]       = make_float2(silu(acc[g][0]), silu(acc[g][1]));
            *(float2*)&g_zs[(size_t)(t0 + 8) * DI + zc] = make_float2(silu(acc[g][2]), silu(acc[g][3]));
        }
    }
}

// ---------------- x_proj via tensor cores ----------------
__global__ void __launch_bounds__(128) xproj_mma()
{
    __shared__ __half sW[48 * 200];
    const int tid = threadIdx.x;
    const int w = tid >> 5, lane = tid & 31;
    const int m0 = blockIdx.x * 64;
    const int nd = m0 >> 12, l0 = m0 & 4095;

    for (int i = tid; i < 48 * 192; i += 128) {
        int r = i / 192, c = i - r * 192;
        sW[r * 200 + c] = g_Wh1[i];
    }
    __syncthreads();

    const __half* X = g_xcT + (size_t)nd * DI * LL;
    const int qr = lane >> 2, qc = (lane & 3) << 1;
    const int tB = l0 + w * 16 + qr;

    float acc[3][2][4];
    #pragma unroll
    for (int g = 0; g < 3; g++)
        #pragma unroll
        for (int t = 0; t < 2; t++)
            #pragma unroll
            for (int q = 0; q < 4; q++) acc[g][t][q] = 0.f;

    #pragma unroll 2
    for (int ks = 0; ks < 12; ks++) {
        const int k = ks * 16 + qc;
        unsigned a[3][4];
        #pragma unroll
        for (int g = 0; g < 3; g++) {
            int r = g * 16 + qr;
            a[g][0] = *(const unsigned*)&sW[r * 200 + k];
            a[g][1] = *(const unsigned*)&sW[(r + 8) * 200 + k];
            a[g][2] = *(const unsigned*)&sW[r * 200 + k + 8];
            a[g][3] = *(const unsigned*)&sW[(r + 8) * 200 + k + 8];
        }
        unsigned bf[2][2];
        #pragma unroll
        for (int tg = 0; tg < 2; tg++) {
            const __half* xp = X + (size_t)k * LL + tB + tg * 8;
            bf[tg][0] = pack2(xp[0], xp[LL]);
            bf[tg][1] = pack2(xp[8 * LL], xp[9 * LL]);
        }
        #pragma unroll
        for (int g = 0; g < 3; g++)
            #pragma unroll
            for (int tg = 0; tg < 2; tg++)
                mma16816(acc[g][tg], a[g], bf[tg]);
    }

    #pragma unroll
    for (int g = 0; g < 3; g++) {
        #pragma unroll
        for (int tg = 0; tg < 2; tg++) {
            int T = m0 + w * 16 + tg * 8 + qc;
            #pragma unroll
            for (int q = 0; q < 4; q++) {
                int nb = g * 16 + qr + ((q >= 2) ? 8 : 0);
                int Tt = T + (q & 1);
                float v = acc[g][tg][q];
                if (nb < RNK)        g_dtm[(size_t)Tt * RNK + nb] = v;
                else if (nb < 38)    g_BC[(size_t)Tt * 32 + (nb - RNK)] = v;
            }
        }
    }
}

// ---------------- out_proj via tensor cores ----------------
__global__ void __launch_bounds__(128) outproj_mma(float* __restrict__ out)
{
    __shared__ __half sA[64 * 200];
    const int tid = threadIdx.x;
    const int w = tid >> 5, lane = tid & 31;
    const int m0 = blockIdx.x * 64;
    const int b = m0 >> 12, p0 = m0 & 4095;

    for (int i = tid; i < 64 * 48; i += 128) {
        int m = i / 48, kq = (i - m * 48) * 4;
        float4 yv = *(const float4*)&g_ycomb[(size_t)(m0 + m) * 192 + kq];
        float4 zv = *(const float4*)&g_zs[(size_t)(m0 + m) * 192 + kq];
        *(__half2*)&sA[m * 200 + kq]     = __floats2half2_rn(yv.x * zv.x, yv.y * zv.y);
        *(__half2*)&sA[m * 200 + kq + 2] = __floats2half2_rn(yv.z * zv.z, yv.w * zv.w);
    }
    __syncthreads();

    const int qr = lane >> 2, qc = (lane & 3) << 1;
    const int rA = w * 16 + qr;

    float acc[12][4];
    #pragma unroll
    for (int g = 0; g < 12; g++)
        #pragma unroll
        for (int q = 0; q < 4; q++) acc[g][q] = 0.f;

    for (int ks = 0; ks < 12; ks++) {
        const int k = ks * 16 + qc;
        unsigned a[4];
        a[0] = *(const unsigned*)&sA[rA * 200 + k];
        a[1] = *(const unsigned*)&sA[(rA + 8) * 200 + k];
        a[2] = *(const unsigned*)&sA[rA * 200 + k + 8];
        a[3] = *(const unsigned*)&sA[(rA + 8) * 200 + k + 8];
        #pragma unroll
        for (int g = 0; g < 12; g++) {
            int n = g * 8 + qr;
            unsigned bf[2];
            bf[0] = *(const unsigned*)&g_Wh2[n * 192 + k];
            bf[1] = *(const unsigned*)&g_Wh2[n * 192 + k + 8];
            mma16816(acc[g], a, bf);
        }
    }

    #pragma unroll
    for (int g = 0; g < 12; g++) {
        int nc = g * 8 + qc;
        int t = p0 + w * 16 + qr;
        out[((size_t)b * 96 + nc)     * 4096 + t]     = acc[g][0];
        out[((size_t)b * 96 + nc + 1) * 4096 + t]     = acc[g][1];
        out[((size_t)b * 96 + nc)     * 4096 + t + 8] = acc[g][2];
        out[((size_t)b * 96 + nc + 1) * 4096 + t + 8] = acc[g][3];
    }
}

// ---------------- K3: depthwise causal conv + silu -> fp16 transposed ----------------
#define CONV_TL 32
__global__ void __launch_bounds__(192) conv_kernel(
    const float* __restrict__ cw, const float* __restrict__ cb)
{
    __shared__ float sbuf[DI][CONV_TL + 1];
    const int d = threadIdx.x;
    const int n = blockIdx.y;
    const int l0 = blockIdx.x * CONV_TL;
    const int b = n & 3, k = n >> 2;
    const float w0 = cw[d * 4 + 0], w1 = cw[d * 4 + 1], w2 = cw[d * 4 + 2], w3 = cw[d * 4 + 3];
    const float bias = cb[d];
    const __half* xb = g_xsh + (size_t)b * LL * DI + d;

    float x1 = (l0 - 3 >= 0) ? __half2float(xb[(size_t)pmap(l0 - 3, k) * DI]) : 0.f;
    float x2 = (l0 - 2 >= 0) ? __half2float(xb[(size_t)pmap(l0 - 2, k) * DI]) : 0.f;
    float x3 = (l0 - 1 >= 0) ? __half2float(xb[(size_t)pmap(l0 - 1, k) * DI]) : 0.f;

    #pragma unroll 4
    for (int l = 0; l < CONV_TL; ++l) {
        float cur = __half2float(xb[(size_t)pmap(l0 + l, k) * DI]);
        float v = bias + w0 * x1 + w1 * x2 + w2 * x3 + w3 * cur;
        v = silu(v);
        sbuf[d][l] = v;
        x1 = x2; x2 = x3; x3 = cur;
    }
    __syncthreads();
    __half* dst = g_xcT + (size_t)n * DI * LL + l0;
    for (int i = threadIdx.x; i < DI * (CONV_TL / 2); i += 192) {
        int dd = i >> 4, l2 = (i & 15) << 1;
        __half2 hv = __floats2half2_rn(sbuf[dd][l2], sbuf[dd][l2 + 1]);
        *(__half2*)(dst + (size_t)dd * LL + l2) = hv;
    }
}

// ---------------- K5: dt_proj + softplus -> fp16 delta (transposed) ----------------
#define DT_TL 256
__global__ void __launch_bounds__(128) dtproj_kernel(
    const float* __restrict__ dtw, const float* __restrict__ dtb)
{
    __shared__ float sdtm[RNK][DT_TL];
    __shared__ float sdtw[RNK][DI];
    const int tid = threadIdx.x;
    const int l0 = blockIdx.x * DT_TL;
    const int n = blockIdx.y;

    for (int i = tid; i < DT_TL * RNK; i += 128) {
        int l = i / RNK, r = i - l * RNK;
        sdtm[r][l] = g_dtm[((size_t)n * LL + l0 + l) * RNK + r];
    }
    for (int i = tid; i < DI * RNK; i += 128) {
        int dd = i / RNK, r = i - dd * RNK;
        sdtw[r][dd] = dtw[i];
    }
    __syncthreads();

    const int la = tid << 1;
    __half* dst = g_dltT + (size_t)n * DI * LL + l0 + la;
    for (int d = 0; d < DI; d++) {
        float s0 = dtb[d], s1 = s0;
        #pragma unroll
        for (int r = 0; r < RNK; r++) {
            float wv = sdtw[r][d];
            s0 += sdtm[r][la] * wv;
            s1 += sdtm[r][la + 1] * wv;
        }
        s0 = (s0 > 20.f) ? s0 : __logf(1.f + __expf(s0));
        s1 = (s1 > 20.f) ? s1 : __logf(1.f + __expf(s1));
        *(__half2*)(dst + (size_t)d * LL) = __floats2half2_rn(s0, s1);
    }
}

// ---------------- chunked selective scan (2 states/lane, 16 d/block) ----------------
__global__ void __launch_bounds__(128) scanA_kernel(const float* __restrict__ A_log)
{
    __shared__ float2 sdu[16][CT + 2];
    __shared__ float2 sB[CT][8];
    const int tid = threadIdx.x;
    const int c = blockIdx.x, dg = blockIdx.y, n = blockIdx.z;
    const int l0 = c * CT, d0 = dg * 16;

    for (int i = tid; i < 16 * (CT / 2); i += 128) {
        int dd = i >> 5, l2 = (i & 31) << 1;
        size_t off = (size_t)n * DI * LL + (size_t)(d0 + dd) * LL + l0 + l2;
        float2 fd = __half22float2(*(const __half2*)(g_dltT + off));
        float2 fu = __half22float2(*(const __half2*)(g_xcT + off));
        sdu[dd][l2]     = make_float2(fd.x, fu.x);
        sdu[dd][l2 + 1] = make_float2(fd.y, fu.y);
    }
    for (int i = tid; i < CT * 8; i += 128) {
        int l = i >> 3, j = i & 7;
        sB[l][j] = *(const float2*)&g_BC[((size_t)n * LL + l0 + l) * 32 + 2 * j];
    }
    const int lane = tid & 31, w = tid >> 5;
    const int j = lane & 7, dloc = (w << 2) | (lane >> 3);
    const int d = d0 + dloc;
    float2 al = *(const float2*)&A_log[d * DS + 2 * j];
    const float cA0 = -expf(al.x) * 1.4426950408889634f;
    const float cA1 = -expf(al.y) * 1.4426950408889634f;
    __syncthreads();

    float h0 = 0.f, h1 = 0.f, S = 0.f;
    #pragma unroll 4
    for (int l = 0; l < CT; ++l) {
        float2 du = sdu[dloc][l];
        float2 Bv = sB[l][j];
        float a0 = exp2f(du.x * cA0);
        float a1 = exp2f(du.x * cA1);
        float du2 = du.x * du.y;
        h0 = a0 * h0 + du2 * Bv.x;
        h1 = a1 * h1 + du2 * Bv.y;
        S += du.x;
    }
    size_t o = ((size_t)(n * NC + c)) * (DI * DS) + d * DS + 2 * j;
    *(float2*)&g_H[o] = make_float2(h0, h1);
    *(float2*)&g_P[o] = make_float2(exp2f(cA0 * S), exp2f(cA1 * S));
}

__global__ void __launch_bounds__(256) scanB_kernel()
{
    const int gid = blockIdx.x * 256 + threadIdx.x;
    const int n = gid / (DI * DS);
    const int ds = gid - n * (DI * DS);
    size_t base = (size_t)n * NC * (DI * DS) + ds;
    float h = 0.f;
    #pragma unroll 4
    for (int cc = 0; cc < NC; ++cc) {
        size_t a = base + (size_t)cc * (DI * DS);
        float Pv = g_P[a], Hv = g_H[a];
        g_H[a] = h;
        h = Pv * h + Hv;
    }
}

__global__ void __launch_bounds__(128) scanC_kernel(
    const float* __restrict__ A_log, const float* __restrict__ Dp)
{
    __shared__ float2 sdu[16][CT + 2];
    __shared__ float2 sB[CT][8];
    __shared__ float2 sC[CT][8];
    __shared__ float sg[CT];
    __shared__ float sv[CT][16];
    __shared__ int sp[CT];
    const int tid = threadIdx.x;
    const int c = blockIdx.x, dg = blockIdx.y, n = blockIdx.z;
    const int l0 = c * CT, d0 = dg * 16;
    const int b = n & 3, k = n >> 2;

    for (int i = tid; i < 16 * (CT / 2); i += 128) {
        int dd = i >> 5, l2 = (i & 31) << 1;
        size_t off = (size_t)n * DI * LL + (size_t)(d0 + dd) * LL + l0 + l2;
        float2 fd = __half22float2(*(const __half2*)(g_dltT + off));
        float2 fu = __half22float2(*(const __half2*)(g_xcT + off));
        sdu[dd][l2]     = make_float2(fd.x, fu.x);
        sdu[dd][l2 + 1] = make_float2(fd.y, fu.y);
    }
    for (int i = tid; i < CT * 8; i += 128) {
        int l = i >> 3, j = i & 7;
        const float* bc = &g_BC[((size_t)n * LL + l0 + l) * 32];
        sB[l][j] = *(const float2*)(bc + 2 * j);
        sC[l][j] = *(const float2*)(bc + 16 + 2 * j);
    }
    if (tid < CT) {
        sp[tid] = pmap(l0 + tid, k);
        sg[tid] = g_gateT[(size_t)n * LL + l0 + tid];
    }
    const int lane = tid & 31, w = tid >> 5;
    const int j = lane & 7, dloc = (w << 2) | (lane >> 3);
    const int d = d0 + dloc;
    float2 al = *(const float2*)&A_log[d * DS + 2 * j];
    const float cA0 = -expf(al.x) * 1.4426950408889634f;
    const float cA1 = -expf(al.y) * 1.4426950408889634f;
    const float Dd = Dp[d];
    __syncthreads();

    float2 hv = *(const float2*)&g_H[((size_t)(n * NC + c)) * (DI * DS) + d * DS + 2 * j];
    float h0 = hv.x, h1 = hv.y;

    #pragma unroll 4
    for (int l = 0; l < CT; ++l) {
        float2 du = sdu[dloc][l];
        float2 Bv = sB[l][j];
        float2 Cv = sC[l][j];
        float a0 = exp2f(du.x * cA0);
        float a1 = exp2f(du.x * cA1);
        float du2 = du.x * du.y;
        h0 = a0 * h0 + du2 * Bv.x;
        h1 = a1 * h1 + du2 * Bv.y;
        float y = h0 * Cv.x + h1 * Cv.y;
        y += __shfl_xor_sync(0xffffffffu, y, 1);
        y += __shfl_xor_sync(0xffffffffu, y, 2);
        y += __shfl_xor_sync(0xffffffffu, y, 4);
        if (j == 0)
            sv[l][dloc] = (y + du.y * Dd) * sg[l];
    }
    __syncthreads();

    float* ycb = g_ycomb + (size_t)b * LL * DI + d0;
    #pragma unroll
    for (int jj = 0; jj < 8; jj++) {
        int i = tid + jj * 128;
        int dd = i & 15, l = i >> 4;
        atomicAdd(ycb + (size_t)sp[l] * DI + dd, sv[l][dd]);
    }
}

// ---------------- launch ----------------
extern "C" void kernel_launch(void* const* d_in, const int* in_sizes, int n_in,
                              void* d_out, int out_size)
{
    const float* x         = (const float*)d_in[0];
    const float* norm_g    = (const float*)d_in[1];
    const float* norm_b    = (const float*)d_in[2];
    const float* gate_w1   = (const float*)d_in[3];
    const float* gate_b1   = (const float*)d_in[4];
    const float* gate_w2   = (const float*)d_in[5];
    const float* gate_b2   = (const float*)d_in[6];
    const float* in_proj_w = (const float*)d_in[7];
    const float* conv_w    = (const float*)d_in[8];
    const float* conv_b    = (const float*)d_in[9];
    const float* x_proj_w  = (const float*)d_in[10];
    const float* dt_proj_w = (const float*)d_in[11];
    const float* dt_proj_b = (const float*)d_in[12];
    const float* A_log     = (const float*)d_in[13];
    const float* Dvec      = (const float*)d_in[14];
    const float* out_proj_w= (const float*)d_in[15];
    float* out = (float*)d_out;

    prep_weights<<<144, 256>>>(x_proj_w, out_proj_w, in_proj_w);
    norm_gate_kernel<<<512, 128>>>(x, norm_g, norm_b, gate_w1, gate_b1, gate_w2, gate_b2);
    inproj_mma<<<256, 256>>>();
    conv_kernel<<<dim3(LL / CONV_TL, NDIR), 192>>>(conv_w, conv_b);
    xproj_mma<<<1024, 128>>>();
    dtproj_kernel<<<dim3(LL / DT_TL, NDIR), 128>>>(dt_proj_w, dt_proj_b);
    scanA_kernel<<<dim3(NC, 12, NDIR), 128>>>(A_log);
    scanB_kernel<<<(NDIR * DI * DS) / 256, 256>>>();
    scanC_kernel<<<dim3(NC, 12, NDIR), 128>>>(A_log, Dvec);
    outproj_mma<<<256, 128>>>(out);
}

// round 10
// speedup vs baseline: 10.2814x; 1.0104x over previous
#include <cuda_runtime.h>
#include <cuda_fp16.h>
#include <math.h>

// ---------------- problem constants ----------------
#define BB    4
#define CDIM  96
#define LL    4096      // 64*64
#define DI    192
#define DS    16
#define RNK   6
#define NDIR  16        // 4 directions * BB
#define CT    64        // chunk length
#define NC    64        // number of chunks

// ---------------- scratch (device globals; no allocation) ----------------
__device__ float  g_xn[BB * LL * CDIM];             // [b][p][c]
__device__ float  g_gateT[(size_t)NDIR * LL];       // [n][l]
__device__ __half g_xsh[(size_t)BB * LL * DI];      // [b][p][d]  xs fp16
__device__ float  g_zs[(size_t)BB * LL * DI];       // [b][p][d]  silu(z) fp32
__device__ __half g_xcT[(size_t)NDIR * DI * LL];    // [n][d][l]  fp16
__device__ __half g_dltT[(size_t)NDIR * DI * LL];   // [n][d][l]  fp16
__device__ float  g_dtm[(size_t)NDIR * LL * RNK];   // [n][l][r]
__device__ float  g_BC[(size_t)NDIR * LL * 32];     // [n][l][B0..15,C0..15]
__device__ float  g_ycomb[(size_t)BB * LL * DI];    // [b][p][d]
__device__ float  g_H[(size_t)NDIR * NC * DI * DS]; // [n][c][d][s]
__device__ float  g_P[(size_t)NDIR * NC * DI * DS]; // [n][c][d][s]
__device__ __half g_Wh1[48 * 192];                  // x_proj_w fp16 (padded 48 rows)
__device__ __half g_Wh2[96 * 192];                  // out_proj_w fp16
__device__ __half g_Whin[384 * 96];                 // in_proj_w fp16

__device__ __forceinline__ int pmap(int l, int k) {
    int lr = (k & 2) ? (LL - 1 - l) : l;
    return (k & 1) ? (((lr & 63) << 6) | (lr >> 6)) : lr;
}

// bare MUFU exp2 (exp2f is a slow software sequence without fast-math)
__device__ __forceinline__ float ex2(float x) {
    float y;
    asm("ex2.approx.f32 %0, %1;" : "=f"(y) : "f"(x));
    return y;
}

__device__ __forceinline__ void mma16816(float* d, const unsigned* a, const unsigned* b) {
    asm volatile("mma.sync.aligned.m16n8k16.row.col.f32.f16.f16.f32 "
        "{%0,%1,%2,%3}, {%4,%5,%6,%7}, {%8,%9}, {%0,%1,%2,%3};"
        : "+f"(d[0]), "+f"(d[1]), "+f"(d[2]), "+f"(d[3])
        : "r"(a[0]), "r"(a[1]), "r"(a[2]), "r"(a[3]), "r"(b[0]), "r"(b[1]));
}
__device__ __forceinline__ unsigned pack2(__half lo, __half hi) {
    __half2 h = __halves2half2(lo, hi);
    return *(unsigned*)&h;
}
__device__ __forceinline__ float silu(float v) { return v / (1.f + __expf(-v)); }

// ---------------- prep: fp16 weight copies ----------------
__global__ void __launch_bounds__(256) prep_weights(
    const float* __restrict__ xw, const float* __restrict__ ow, const float* __restrict__ iw)
{
    int i = blockIdx.x * 256 + threadIdx.x;
    if (i < 48 * 192) {
        int r = i / 192, c = i - r * 192;
        g_Wh1[i] = __float2half(r < 38 ? xw[r * 192 + c] : 0.f);
    }
    if (i < 96 * 192) g_Wh2[i] = __float2half(ow[i]);
    if (i < 384 * 96) g_Whin[i] = __float2half(iw[i]);
}

// ---------------- K1: layernorm + gate MLP (+ zero ycomb, scatter gateT) ----------------
__global__ void __launch_bounds__(128) norm_gate_kernel(
    const float* __restrict__ x, const float* __restrict__ ng, const float* __restrict__ nb,
    const float* __restrict__ w1, const float* __restrict__ b1,
    const float* __restrict__ w2, const float* __restrict__ b2)
{
    __shared__ float xs_s[CDIM][33];
    __shared__ float w1_s[24 * 96];
    const int tid = threadIdx.x;
    const int P0 = blockIdx.x * 32;
    const int b = P0 >> 12, p0 = P0 & 4095;

    {
        size_t base = (size_t)blockIdx.x * 6144;
        for (int i = tid; i < 6144; i += 128) g_ycomb[base + i] = 0.f;
    }
    for (int i = tid; i < 96 * 32; i += 128) {
        int c = i >> 5, pi = i & 31;
        xs_s[c][pi] = x[((size_t)b * 96 + c) * 4096 + p0 + pi];
    }
    for (int i = tid; i < 24 * 96; i += 128) w1_s[i] = w1[i];
    __syncthreads();

    if (tid < 32) {
        const int lane = tid;
        float mu = 0.f;
        #pragma unroll
        for (int c = 0; c < 96; c++) mu += xs_s[c][lane];
        mu *= (1.f / 96.f);
        float var = 0.f;
        #pragma unroll
        for (int c = 0; c < 96; c++) { float dv = xs_s[c][lane] - mu; var += dv * dv; }
        var *= (1.f / 96.f);
        const float inv = rsqrtf(var + 1e-5f);
        #pragma unroll
        for (int c = 0; c < 96; c++)
            xs_s[c][lane] = (xs_s[c][lane] - mu) * inv * ng[c] + nb[c];

        float hbuf[24];
        #pragma unroll 4
        for (int jj = 0; jj < 24; jj++) {
            float s = b1[jj];
            for (int c = 0; c < 96; c++) s += xs_s[c][lane] * w1_s[jj * 96 + c];
            hbuf[jj] = tanhf(s);
        }
        float lg[4];
        #pragma unroll
        for (int q = 0; q < 4; q++) {
            float s = b2[q];
            #pragma unroll
            for (int jj = 0; jj < 24; jj++) s += hbuf[jj] * w2[q * 24 + jj];
            lg[q] = s;
        }
        float m = fmaxf(fmaxf(lg[0], lg[1]), fmaxf(lg[2], lg[3]));
        float e[4], se = 0.f;
        #pragma unroll
        for (int q = 0; q < 4; q++) { e[q] = __expf(lg[q] - m); se += e[q]; }
        float rs = 1.f / se;
        const int p = p0 + lane;
        #pragma unroll
        for (int q = 0; q < 4; q++) {
            int l = pmap(p, q);
            g_gateT[(size_t)(q * 4 + b) * LL + l] = e[q] * rs;
        }
    }
    __syncthreads();
    for (int i = tid; i < 32 * 96; i += 128) {
        int pi = i / 96, c = i % 96;
        g_xn[(size_t)(b * 4096 + p0 + pi) * 96 + c] = xs_s[c][pi];
    }
}

// ---------------- in_proj via tensor cores ----------------
__global__ void __launch_bounds__(256) inproj_mma()
{
    __shared__ __half sA[64][104];
    const int tid = threadIdx.x;
    const int w = tid >> 5, lane = tid & 31;
    const int m0 = blockIdx.x * 64;

    for (int i = tid; i < 64 * 24; i += 256) {
        int m = i / 24, kq = (i - m * 24) * 4;
        float4 v = *(const float4*)&g_xn[(size_t)(m0 + m) * 96 + kq];
        *(__half2*)&sA[m][kq]     = __floats2half2_rn(v.x, v.y);
        *(__half2*)&sA[m][kq + 2] = __floats2half2_rn(v.z, v.w);
    }
    __syncthreads();

    const int qr = lane >> 2, qc = (lane & 3) << 1;
    const int wt = w & 3, nh = (w >> 2) * 192;
    const int rA = wt * 16 + qr;

    float acc[24][4];
    #pragma unroll
    for (int g = 0; g < 24; g++)
        #pragma unroll
        for (int q = 0; q < 4; q++) acc[g][q] = 0.f;

    #pragma unroll
    for (int ks = 0; ks < 6; ks++) {
        const int k = ks * 16 + qc;
        unsigned a[4];
        a[0] = *(const unsigned*)&sA[rA][k];
        a[1] = *(const unsigned*)&sA[rA + 8][k];
        a[2] = *(const unsigned*)&sA[rA][k + 8];
        a[3] = *(const unsigned*)&sA[rA + 8][k + 8];
        #pragma unroll
        for (int g = 0; g < 24; g++) {
            int n = nh + g * 8 + qr;
            unsigned bf[2];
            bf[0] = *(const unsigned*)&g_Whin[n * 96 + k];
            bf[1] = *(const unsigned*)&g_Whin[n * 96 + k + 8];
            mma16816(acc[g], a, bf);
        }
    }

    const int t0 = m0 + wt * 16 + qr;
    #pragma unroll
    for (int g = 0; g < 24; g++) {
        int cn = nh + g * 8 + qc;
        if (nh == 0) {
            *(__half2*)&g_xsh[(size_t)t0 * DI + cn]       = __floats2half2_rn(acc[g][0], acc[g][1]);
            *(__half2*)&g_xsh[(size_t)(t0 + 8) * DI + cn] = __floats2half2_rn(acc[g][2], acc[g][3]);
        } else {
            int zc = cn - 192;
            *(float2*)&g_zs[(size_t)t0 * DI + zc]       = make_float2(silu(acc[g][0]), silu(acc[g][1]));
            *(float2*)&g_zs[(size_t)(t0 + 8) * DI + zc] = make_float2(silu(acc[g][2]), silu(acc[g][3]));
        }
    }
}

// ---------------- x_proj via tensor cores ----------------
__global__ void __launch_bounds__(128) xproj_mma()
{
    __shared__ __half sW[48 * 200];
    const int tid = threadIdx.x;
    const int w = tid >> 5, lane = tid & 31;
    const int m0 = blockIdx.x * 64;
    const int nd = m0 >> 12, l0 = m0 & 4095;

    for (int i = tid; i < 48 * 192; i += 128) {
        int r = i / 192, c = i - r * 192;
        sW[r * 200 + c] = g_Wh1[i];
    }
    __syncthreads();

    const __half* X = g_xcT + (size_t)nd * DI * LL;
    const int qr = lane >> 2, qc = (lane & 3) << 1;
    const int tB = l0 + w * 16 + qr;

    float acc[3][2][4];
    #pragma unroll
    for (int g = 0; g < 3; g++)
        #pragma unroll
        for (int t = 0; t < 2; t++)
            #pragma unroll
            for (int q = 0; q < 4; q++) acc[g][t][q] = 0.f;

    #pragma unroll 2
    for (int ks = 0; ks < 12; ks++) {
        const int k = ks * 16 + qc;
        unsigned a[3][4];
        #pragma unroll
        for (int g = 0; g < 3; g++) {
            int r = g * 16 + qr;
            a[g][0] = *(const unsigned*)&sW[r * 200 + k];
            a[g][1] = *(const unsigned*)&sW[(r + 8) * 200 + k];
            a[g][2] = *(const unsigned*)&sW[r * 200 + k + 8];
            a[g][3] = *(const unsigned*)&sW[(r + 8) * 200 + k + 8];
        }
        unsigned bf[2][2];
        #pragma unroll
        for (int tg = 0; tg < 2; tg++) {
            const __half* xp = X + (size_t)k * LL + tB + tg * 8;
            bf[tg][0] = pack2(xp[0], xp[LL]);
            bf[tg][1] = pack2(xp[8 * LL], xp[9 * LL]);
        }
        #pragma unroll
        for (int g = 0; g < 3; g++)
            #pragma unroll
            for (int tg = 0; tg < 2; tg++)
                mma16816(acc[g][tg], a[g], bf[tg]);
    }

    #pragma unroll
    for (int g = 0; g < 3; g++) {
        #pragma unroll
        for (int tg = 0; tg < 2; tg++) {
            int T = m0 + w * 16 + tg * 8 + qc;
            #pragma unroll
            for (int q = 0; q < 4; q++) {
                int nb = g * 16 + qr + ((q >= 2) ? 8 : 0);
                int Tt = T + (q & 1);
                float v = acc[g][tg][q];
                if (nb < RNK)        g_dtm[(size_t)Tt * RNK + nb] = v;
                else if (nb < 38)    g_BC[(size_t)Tt * 32 + (nb - RNK)] = v;
            }
        }
    }
}

// ---------------- out_proj via tensor cores ----------------
__global__ void __launch_bounds__(128) outproj_mma(float* __restrict__ out)
{
    __shared__ __half sA[64 * 200];
    const int tid = threadIdx.x;
    const int w = tid >> 5, lane = tid & 31;
    const int m0 = blockIdx.x * 64;
    const int b = m0 >> 12, p0 = m0 & 4095;

    for (int i = tid; i < 64 * 48; i += 128) {
        int m = i / 48, kq = (i - m * 48) * 4;
        float4 yv = *(const float4*)&g_ycomb[(size_t)(m0 + m) * 192 + kq];
        float4 zv = *(const float4*)&g_zs[(size_t)(m0 + m) * 192 + kq];
        *(__half2*)&sA[m * 200 + kq]     = __floats2half2_rn(yv.x * zv.x, yv.y * zv.y);
        *(__half2*)&sA[m * 200 + kq + 2] = __floats2half2_rn(yv.z * zv.z, yv.w * zv.w);
    }
    __syncthreads();

    const int qr = lane >> 2, qc = (lane & 3) << 1;
    const int rA = w * 16 + qr;

    float acc[12][4];
    #pragma unroll
    for (int g = 0; g < 12; g++)
        #pragma unroll
        for (int q = 0; q < 4; q++) acc[g][q] = 0.f;

    for (int ks = 0; ks < 12; ks++) {
        const int k = ks * 16 + qc;
        unsigned a[4];
        a[0] = *(const unsigned*)&sA[rA * 200 + k];
        a[1] = *(const unsigned*)&sA[(rA + 8) * 200 + k];
        a[2] = *(const unsigned*)&sA[rA * 200 + k + 8];
        a[3] = *(const unsigned*)&sA[(rA + 8) * 200 + k + 8];
        #pragma unroll
        for (int g = 0; g < 12; g++) {
            int n = g * 8 + qr;
            unsigned bf[2];
            bf[0] = *(const unsigned*)&g_Wh2[n * 192 + k];
            bf[1] = *(const unsigned*)&g_Wh2[n * 192 + k + 8];
            mma16816(acc[g], a, bf);
        }
    }

    #pragma unroll
    for (int g = 0; g < 12; g++) {
        int nc = g * 8 + qc;
        int t = p0 + w * 16 + qr;
        out[((size_t)b * 96 + nc)     * 4096 + t]     = acc[g][0];
        out[((size_t)b * 96 + nc + 1) * 4096 + t]     = acc[g][1];
        out[((size_t)b * 96 + nc)     * 4096 + t + 8] = acc[g][2];
        out[((size_t)b * 96 + nc + 1) * 4096 + t + 8] = acc[g][3];
    }
}

// ---------------- K3: depthwise causal conv + silu -> fp16 transposed ----------------
// pmap is affine within a 32-aligned tile: p(l) = pstart + l*pstep
#define CONV_TL 32
__global__ void __launch_bounds__(192) conv_kernel(
    const float* __restrict__ cw, const float* __restrict__ cb)
{
    __shared__ float sbuf[DI][CONV_TL + 1];
    const int d = threadIdx.x;
    const int n = blockIdx.y;
    const int l0 = blockIdx.x * CONV_TL;
    const int b = n & 3, k = n >> 2;
    const float w0 = cw[d * 4 + 0], w1 = cw[d * 4 + 1], w2 = cw[d * 4 + 2], w3 = cw[d * 4 + 3];
    const float bias = cb[d];
    const __half* xb = g_xsh + (size_t)b * LL * DI + d;

    float x1 = (l0 - 3 >= 0) ? __half2float(xb[(size_t)pmap(l0 - 3, k) * DI]) : 0.f;
    float x2 = (l0 - 2 >= 0) ? __half2float(xb[(size_t)pmap(l0 - 2, k) * DI]) : 0.f;
    float x3 = (l0 - 1 >= 0) ? __half2float(xb[(size_t)pmap(l0 - 1, k) * DI]) : 0.f;

    int pstep = (k & 1) ? 64 : 1;
    if (k & 2) pstep = -pstep;
    const __half* cp = xb + (size_t)pmap(l0, k) * DI;
    const ptrdiff_t pinc = (ptrdiff_t)pstep * DI;

    #pragma unroll 8
    for (int l = 0; l < CONV_TL; ++l) {
        float cur = __half2float(*cp);
        cp += pinc;
        float v = bias + w0 * x1 + w1 * x2 + w2 * x3 + w3 * cur;
        v = silu(v);
        sbuf[d][l] = v;
        x1 = x2; x2 = x3; x3 = cur;
    }
    __syncthreads();
    __half* dst = g_xcT + (size_t)n * DI * LL + l0;
    for (int i = threadIdx.x; i < DI * (CONV_TL / 2); i += 192) {
        int dd = i >> 4, l2 = (i & 15) << 1;
        __half2 hv = __floats2half2_rn(sbuf[dd][l2], sbuf[dd][l2 + 1]);
        *(__half2*)(dst + (size_t)dd * LL + l2) = hv;
    }
}

// ---------------- K5: dt_proj + softplus -> fp16 delta (transposed) ----------------
#define DT_TL 256
__global__ void __launch_bounds__(128) dtproj_kernel(
    const float* __restrict__ dtw, const float* __restrict__ dtb)
{
    __shared__ float sdtm[RNK][DT_TL];
    __shared__ float sdtw[RNK][DI];
    const int tid = threadIdx.x;
    const int l0 = blockIdx.x * DT_TL;
    const int n = blockIdx.y;

    for (int i = tid; i < DT_TL * RNK; i += 128) {
        int l = i / RNK, r = i - l * RNK;
        sdtm[r][l] = g_dtm[((size_t)n * LL + l0 + l) * RNK + r];
    }
    for (int i = tid; i < DI * RNK; i += 128) {
        int dd = i / RNK, r = i - dd * RNK;
        sdtw[r][dd] = dtw[i];
    }
    __syncthreads();

    const int la = tid << 1;
    __half* dst = g_dltT + (size_t)n * DI * LL + l0 + la;
    for (int d = 0; d < DI; d++) {
        float s0 = dtb[d], s1 = s0;
        #pragma unroll
        for (int r = 0; r < RNK; r++) {
            float wv = sdtw[r][d];
            s0 += sdtm[r][la] * wv;
            s1 += sdtm[r][la + 1] * wv;
        }
        s0 = (s0 > 20.f) ? s0 : __logf(1.f + __expf(s0));
        s1 = (s1 > 20.f) ? s1 : __logf(1.f + __expf(s1));
        *(__half2*)(dst + (size_t)d * LL) = __floats2half2_rn(s0, s1);
    }
}

// ---------------- chunked selective scan (2 states/lane, 16 d/block) ----------------
__global__ void __launch_bounds__(128) scanA_kernel(const float* __restrict__ A_log)
{
    __shared__ float2 sdu[16][CT + 2];
    __shared__ float2 sB[CT][8];
    const int tid = threadIdx.x;
    const int c = blockIdx.x, dg = blockIdx.y, n = blockIdx.z;
    const int l0 = c * CT, d0 = dg * 16;

    for (int i = tid; i < 16 * (CT / 2); i += 128) {
        int dd = i >> 5, l2 = (i & 31) << 1;
        size_t off = (size_t)n * DI * LL + (size_t)(d0 + dd) * LL + l0 + l2;
        float2 fd = __half22float2(*(const __half2*)(g_dltT + off));
        float2 fu = __half22float2(*(const __half2*)(g_xcT + off));
        sdu[dd][l2]     = make_float2(fd.x, fu.x);
        sdu[dd][l2 + 1] = make_float2(fd.y, fu.y);
    }
    for (int i = tid; i < CT * 8; i += 128) {
        int l = i >> 3, j = i & 7;
        sB[l][j] = *(const float2*)&g_BC[((size_t)n * LL + l0 + l) * 32 + 2 * j];
    }
    const int lane = tid & 31, w = tid >> 5;
    const int j = lane & 7, dloc = (w << 2) | (lane >> 3);
    const int d = d0 + dloc;
    float2 al = *(const float2*)&A_log[d * DS + 2 * j];
    const float cA0 = -expf(al.x) * 1.4426950408889634f;
    const float cA1 = -expf(al.y) * 1.4426950408889634f;
    __syncthreads();

    float h0 = 0.f, h1 = 0.f, S = 0.f;
    #pragma unroll 4
    for (int l = 0; l < CT; ++l) {
        float2 du = sdu[dloc][l];
        float2 Bv = sB[l][j];
        float a0 = ex2(du.x * cA0);
        float a1 = ex2(du.x * cA1);
        float du2 = du.x * du.y;
        h0 = a0 * h0 + du2 * Bv.x;
        h1 = a1 * h1 + du2 * Bv.y;
        S += du.x;
    }
    size_t o = ((size_t)(n * NC + c)) * (DI * DS) + d * DS + 2 * j;
    *(float2*)&g_H[o] = make_float2(h0, h1);
    *(float2*)&g_P[o] = make_float2(ex2(cA0 * S), ex2(cA1 * S));
}

__global__ void __launch_bounds__(256) scanB_kernel()
{
    const int gid = blockIdx.x * 256 + threadIdx.x;
    const int n = gid / (DI * DS);
    const int ds = gid - n * (DI * DS);
    size_t base = (size_t)n * NC * (DI * DS) + ds;
    float h = 0.f;
    #pragma unroll 4
    for (int cc = 0; cc < NC; ++cc) {
        size_t a = base + (size_t)cc * (DI * DS);
        float Pv = g_P[a], Hv = g_H[a];
        g_H[a] = h;
        h = Pv * h + Hv;
    }
}

__global__ void __launch_bounds__(128) scanC_kernel(
    const float* __restrict__ A_log, const float* __restrict__ Dp)
{
    __shared__ float2 sdu[16][CT + 2];
    __shared__ float2 sB[CT][8];
    __shared__ float2 sC[CT][8];
    __shared__ float sg[CT];
    __shared__ float sv[CT][16];
    __shared__ int sp[CT];
    const int tid = threadIdx.x;
    const int c = blockIdx.x, dg = blockIdx.y, n = blockIdx.z;
    const int l0 = c * CT, d0 = dg * 16;
    const int b = n & 3, k = n >> 2;

    for (int i = tid; i < 16 * (CT / 2); i += 128) {
        int dd = i >> 5, l2 = (i & 31) << 1;
        size_t off = (size_t)n * DI * LL + (size_t)(d0 + dd) * LL + l0 + l2;
        float2 fd = __half22float2(*(const __half2*)(g_dltT + off));
        float2 fu = __half22float2(*(const __half2*)(g_xcT + off));
        sdu[dd][l2]     = make_float2(fd.x, fu.x);
        sdu[dd][l2 + 1] = make_float2(fd.y, fu.y);
    }
    for (int i = tid; i < CT * 8; i += 128) {
        int l = i >> 3, j = i & 7;
        const float* bc = &g_BC[((size_t)n * LL + l0 + l) * 32];
        sB[l][j] = *(const float2*)(bc + 2 * j);
        sC[l][j] = *(const float2*)(bc + 16 + 2 * j);
    }
    if (tid < CT) {
        sp[tid] = pmap(l0 + tid, k);
        sg[tid] = g_gateT[(size_t)n * LL + l0 + tid];
    }
    const int lane = tid & 31, w = tid >> 5;
    const int j = lane & 7, dloc = (w << 2) | (lane >> 3);
    const int d = d0 + dloc;
    float2 al = *(const float2*)&A_log[d * DS + 2 * j];
    const float cA0 = -expf(al.x) * 1.4426950408889634f;
    const float cA1 = -expf(al.y) * 1.4426950408889634f;
    const float Dd = Dp[d];
    __syncthreads();

    float2 hv = *(const float2*)&g_H[((size_t)(n * NC + c)) * (DI * DS) + d * DS + 2 * j];
    float h0 = hv.x, h1 = hv.y;

    #pragma unroll 4
    for (int l = 0; l < CT; ++l) {
        float2 du = sdu[dloc][l];
        float2 Bv = sB[l][j];
        float2 Cv = sC[l][j];
        float a0 = ex2(du.x * cA0);
        float a1 = ex2(du.x * cA1);
        float du2 = du.x * du.y;
        h0 = a0 * h0 + du2 * Bv.x;
        h1 = a1 * h1 + du2 * Bv.y;
        float y = h0 * Cv.x + h1 * Cv.y;
        y += __shfl_xor_sync(0xffffffffu, y, 1);
        y += __shfl_xor_sync(0xffffffffu, y, 2);
        y += __shfl_xor_sync(0xffffffffu, y, 4);
        if (j == 0)
            sv[l][dloc] = (y + du.y * Dd) * sg[l];
    }
    __syncthreads();

    float* ycb = g_ycomb + (size_t)b * LL * DI + d0;
    #pragma unroll
    for (int jj = 0; jj < 8; jj++) {
        int i = tid + jj * 128;
        int dd = i & 15, l = i >> 4;
        atomicAdd(ycb + (size_t)sp[l] * DI + dd, sv[l][dd]);
    }
}

// ---------------- launch ----------------
extern "C" void kernel_launch(void* const* d_in, const int* in_sizes, int n_in,
                              void* d_out, int out_size)
{
    const float* x         = (const float*)d_in[0];
    const float* norm_g    = (const float*)d_in[1];
    const float* norm_b    = (const float*)d_in[2];
    const float* gate_w1   = (const float*)d_in[3];
    const float* gate_b1   = (const float*)d_in[4];
    const float* gate_w2   = (const float*)d_in[5];
    const float* gate_b2   = (const float*)d_in[6];
    const float* in_proj_w = (const float*)d_in[7];
    const float* conv_w    = (const float*)d_in[8];
    const float* conv_b    = (const float*)d_in[9];
    const float* x_proj_w  = (const float*)d_in[10];
    const float* dt_proj_w = (const float*)d_in[11];
    const float* dt_proj_b = (const float*)d_in[12];
    const float* A_log     = (const float*)d_in[13];
    const float* Dvec      = (const float*)d_in[14];
    const float* out_proj_w= (const float*)d_in[15];
    float* out = (float*)d_out;

    prep_weights<<<144, 256>>>(x_proj_w, out_proj_w, in_proj_w);
    norm_gate_kernel<<<512, 128>>>(x, norm_g, norm_b, gate_w1, gate_b1, gate_w2, gate_b2);
    inproj_mma<<<256, 256>>>();
    conv_kernel<<<dim3(LL / CONV_TL, NDIR), 192>>>(conv_w, conv_b);
    xproj_mma<<<1024, 128>>>();
    dtproj_kernel<<<dim3(LL / DT_TL, NDIR), 128>>>(dt_proj_w, dt_proj_b);
    scanA_kernel<<<dim3(NC, 12, NDIR), 128>>>(A_log);
    scanB_kernel<<<(NDIR * DI * DS) / 256, 256>>>();
    scanC_kernel<<<dim3(NC, 12, NDIR), 128>>>(A_log, Dvec);
    outproj_mma<<<256, 128>>>(out);
}

// round 13
// speedup vs baseline: 10.9774x; 1.0677x over previous
#include <cuda_runtime.h>
#include <cuda_fp16.h>
#include <math.h>

// ---------------- problem constants ----------------
#define BB    4
#define CDIM  96
#define LL    4096      // 64*64
#define DI    192
#define DS    16
#define RNK   6
#define NDIR  16        // 4 directions * BB
#define CT    64        // chunk length
#define NC    64        // number of chunks

// ---------------- scratch (device globals; no allocation) ----------------
__device__ float  g_xn[BB * LL * CDIM];             // [b][p][c]
__device__ float  g_gateT[(size_t)NDIR * LL];       // [n][l]
__device__ __half g_xsh[(size_t)BB * LL * DI];      // [b][p][d]  xs fp16
__device__ float  g_zs[(size_t)BB * LL * DI];       // [b][p][d]  silu(z) fp32
__device__ __half g_xcT[(size_t)NDIR * DI * LL];    // [n][d][l]  fp16
__device__ float  g_dtm[(size_t)NDIR * LL * RNK];   // [n][l][r]
__device__ float  g_BC[(size_t)NDIR * LL * 32];     // [n][l][B0..15,C0..15]
__device__ float  g_ycomb[(size_t)BB * LL * DI];    // [b][p][d]
__device__ float  g_H[(size_t)NDIR * NC * DI * DS]; // [n][c][d][s]
__device__ float  g_P[(size_t)NDIR * NC * DI * DS]; // [n][c][d][s]
__device__ __half g_Wh1[48 * 192];                  // x_proj_w fp16 (padded 48 rows)
__device__ __half g_Wh2[96 * 192];                  // out_proj_w fp16
__device__ __half g_Whin[384 * 96];                 // in_proj_w fp16

__device__ __forceinline__ int pmap(int l, int k) {
    int lr = (k & 2) ? (LL - 1 - l) : l;
    return (k & 1) ? (((lr & 63) << 6) | (lr >> 6)) : lr;
}

__device__ __forceinline__ float ex2(float x) {
    float y;
    asm("ex2.approx.f32 %0, %1;" : "=f"(y) : "f"(x));
    return y;
}

__device__ __forceinline__ void mma16816(float* d, const unsigned* a, const unsigned* b) {
    asm volatile("mma.sync.aligned.m16n8k16.row.col.f32.f16.f16.f32 "
        "{%0,%1,%2,%3}, {%4,%5,%6,%7}, {%8,%9}, {%0,%1,%2,%3};"
        : "+f"(d[0]), "+f"(d[1]), "+f"(d[2]), "+f"(d[3])
        : "r"(a[0]), "r"(a[1]), "r"(a[2]), "r"(a[3]), "r"(b[0]), "r"(b[1]));
}
__device__ __forceinline__ unsigned pack2(__half lo, __half hi) {
    __half2 h = __halves2half2(lo, hi);
    return *(unsigned*)&h;
}
__device__ __forceinline__ float silu(float v) { return v / (1.f + __expf(-v)); }
__device__ __forceinline__ float softplus_f(float s) {
    return (s > 20.f) ? s : __logf(1.f + __expf(s));
}

// ---------------- K1: layernorm + gate MLP (+ zero ycomb, gateT, weight prep) ----------------
__global__ void __launch_bounds__(128) norm_gate_kernel(
    const float* __restrict__ x, const float* __restrict__ ng, const float* __restrict__ nb,
    const float* __restrict__ w1, const float* __restrict__ b1,
    const float* __restrict__ w2, const float* __restrict__ b2,
    const float* __restrict__ xw, const float* __restrict__ ow, const float* __restrict__ iw)
{
    __shared__ float xs_s[CDIM][33];
    __shared__ float w1_s[24 * 96];
    const int tid = threadIdx.x;
    const int P0 = blockIdx.x * 32;
    const int b = P0 >> 12, p0 = P0 & 4095;

    // folded weight prep: 64512 fp16 conversions spread over 512 blocks
    {
        int i = blockIdx.x * 126 + tid;
        if (tid < 126 && i < 64512) {
            if (i < 9216)        g_Wh1[i] = __float2half(i < 38 * 192 ? xw[i] : 0.f);
            else if (i < 27648)  g_Wh2[i - 9216] = __float2half(ow[i - 9216]);
            else                 g_Whin[i - 27648] = __float2half(iw[i - 27648]);
        }
    }
    {
        size_t base = (size_t)blockIdx.x * 6144;
        for (int i = tid; i < 6144; i += 128) g_ycomb[base + i] = 0.f;
    }
    for (int i = tid; i < 96 * 32; i += 128) {
        int c = i >> 5, pi = i & 31;
        xs_s[c][pi] = x[((size_t)b * 96 + c) * 4096 + p0 + pi];
    }
    for (int i = tid; i < 24 * 96; i += 128) w1_s[i] = w1[i];
    __syncthreads();

    if (tid < 32) {
        const int lane = tid;
        float mu = 0.f;
        #pragma unroll
        for (int c = 0; c < 96; c++) mu += xs_s[c][lane];
        mu *= (1.f / 96.f);
        float var = 0.f;
        #pragma unroll
        for (int c = 0; c < 96; c++) { float dv = xs_s[c][lane] - mu; var += dv * dv; }
        var *= (1.f / 96.f);
        const float inv = rsqrtf(var + 1e-5f);
        #pragma unroll
        for (int c = 0; c < 96; c++)
            xs_s[c][lane] = (xs_s[c][lane] - mu) * inv * ng[c] + nb[c];

        float hbuf[24];
        #pragma unroll 4
        for (int jj = 0; jj < 24; jj++) {
            float s = b1[jj];
            for (int c = 0; c < 96; c++) s += xs_s[c][lane] * w1_s[jj * 96 + c];
            hbuf[jj] = tanhf(s);
        }
        float lg[4];
        #pragma unroll
        for (int q = 0; q < 4; q++) {
            float s = b2[q];
            #pragma unroll
            for (int jj = 0; jj < 24; jj++) s += hbuf[jj] * w2[q * 24 + jj];
            lg[q] = s;
        }
        float m = fmaxf(fmaxf(lg[0], lg[1]), fmaxf(lg[2], lg[3]));
        float e[4], se = 0.f;
        #pragma unroll
        for (int q = 0; q < 4; q++) { e[q] = __expf(lg[q] - m); se += e[q]; }
        float rs = 1.f / se;
        const int p = p0 + lane;
        #pragma unroll
        for (int q = 0; q < 4; q++) {
            int l = pmap(p, q);
            g_gateT[(size_t)(q * 4 + b) * LL + l] = e[q] * rs;
        }
    }
    __syncthreads();
    for (int i = tid; i < 32 * 96; i += 128) {
        int pi = i / 96, c = i % 96;
        g_xn[(size_t)(b * 4096 + p0 + pi) * 96 + c] = xs_s[c][pi];
    }
}

// ---------------- in_proj via tensor cores ----------------
__global__ void __launch_bounds__(256) inproj_mma()
{
    __shared__ __half sA[64][104];
    const int tid = threadIdx.x;
    const int w = tid >> 5, lane = tid & 31;
    const int m0 = blockIdx.x * 64;

    for (int i = tid; i < 64 * 24; i += 256) {
        int m = i / 24, kq = (i - m * 24) * 4;
        float4 v = *(const float4*)&g_xn[(size_t)(m0 + m) * 96 + kq];
        *(__half2*)&sA[m][kq]     = __floats2half2_rn(v.x, v.y);
        *(__half2*)&sA[m][kq + 2] = __floats2half2_rn(v.z, v.w);
    }
    __syncthreads();

    const int qr = lane >> 2, qc = (lane & 3) << 1;
    const int wt = w & 3, nh = (w >> 2) * 192;
    const int rA = wt * 16 + qr;

    float acc[24][4];
    #pragma unroll
    for (int g = 0; g < 24; g++)
        #pragma unroll
        for (int q = 0; q < 4; q++) acc[g][q] = 0.f;

    #pragma unroll
    for (int ks = 0; ks < 6; ks++) {
        const int k = ks * 16 + qc;
        unsigned a[4];
        a[0] = *(const unsigned*)&sA[rA][k];
        a[1] = *(const unsigned*)&sA[rA + 8][k];
        a[2] = *(const unsigned*)&sA[rA][k + 8];
        a[3] = *(const unsigned*)&sA[rA + 8][k + 8];
        #pragma unroll
        for (int g = 0; g < 24; g++) {
            int n = nh + g * 8 + qr;
            unsigned bf[2];
            bf[0] = *(const unsigned*)&g_Whin[n * 96 + k];
            bf[1] = *(const unsigned*)&g_Whin[n * 96 + k + 8];
            mma16816(acc[g], a, bf);
        }
    }

    const int t0 = m0 + wt * 16 + qr;
    #pragma unroll
    for (int g = 0; g < 24; g++) {
        int cn = nh + g * 8 + qc;
        if (nh == 0) {
            *(__half2*)&g_xsh[(size_t)t0 * DI + cn]       = __floats2half2_rn(acc[g][0], acc[g][1]);
            *(__half2*)&g_xsh[(size_t)(t0 + 8) * DI + cn] = __floats2half2_rn(acc[g][2], acc[g][3]);
        } else {
            int zc = cn - 192;
            *(float2*)&g_zs[(size_t)t0 * DI + zc]       = make_float2(silu(acc[g][0]), silu(acc[g][1]));
            *(float2*)&g_zs[(size_t)(t0 + 8) * DI + zc] = make_float2(silu(acc[g][2]), silu(acc[g][3]));
        }
    }
}

// ---------------- K3: depthwise causal conv + silu -> fp16 transposed ----------------
#define CONV_TL 32
__global__ void __launch_bounds__(192) conv_kernel(
    const float* __restrict__ cw, const float* __restrict__ cb)
{
    __shared__ float sbuf[DI][CONV_TL + 1];
    const int d = threadIdx.x;
    const int n = blockIdx.y;
    const int l0 = blockIdx.x * CONV_TL;
    const int b = n & 3, k = n >> 2;
    const float w0 = cw[d * 4 + 0], w1 = cw[d * 4 + 1], w2 = cw[d * 4 + 2], w3 = cw[d * 4 + 3];
    const float bias = cb[d];
    const __half* xb = g_xsh + (size_t)b * LL * DI + d;

    float x1 = (l0 - 3 >= 0) ? __half2float(xb[(size_t)pmap(l0 - 3, k) * DI]) : 0.f;
    float x2 = (l0 - 2 >= 0) ? __half2float(xb[(size_t)pmap(l0 - 2, k) * DI]) : 0.f;
    float x3 = (l0 - 1 >= 0) ? __half2float(xb[(size_t)pmap(l0 - 1, k) * DI]) : 0.f;

    int pstep = (k & 1) ? 64 : 1;
    if (k & 2) pstep = -pstep;
    const __half* cp = xb + (size_t)pmap(l0, k) * DI;
    const ptrdiff_t pinc = (ptrdiff_t)pstep * DI;

    #pragma unroll 8
    for (int l = 0; l < CONV_TL; ++l) {
        float cur = __half2float(*cp);
        cp += pinc;
        float v = bias + w0 * x1 + w1 * x2 + w2 * x3 + w3 * cur;
        v = silu(v);
        sbuf[d][l] = v;
        x1 = x2; x2 = x3; x3 = cur;
    }
    __syncthreads();
    __half* dst = g_xcT + (size_t)n * DI * LL + l0;
    for (int i = threadIdx.x; i < DI * (CONV_TL / 2); i += 192) {
        int dd = i >> 4, l2 = (i & 15) << 1;
        __half2 hv = __floats2half2_rn(sbuf[dd][l2], sbuf[dd][l2 + 1]);
        *(__half2*)(dst + (size_t)dd * LL + l2) = hv;
    }
}

// ---------------- x_proj via tensor cores ----------------
__global__ void __launch_bounds__(128) xproj_mma()
{
    __shared__ __half sW[48 * 200];
    const int tid = threadIdx.x;
    const int w = tid >> 5, lane = tid & 31;
    const int m0 = blockIdx.x * 64;
    const int nd = m0 >> 12, l0 = m0 & 4095;

    for (int i = tid; i < 48 * 192; i += 128) {
        int r = i / 192, c = i - r * 192;
        sW[r * 200 + c] = g_Wh1[i];
    }
    __syncthreads();

    const __half* X = g_xcT + (size_t)nd * DI * LL;
    const int qr = lane >> 2, qc = (lane & 3) << 1;
    const int tB = l0 + w * 16 + qr;

    float acc[3][2][4];
    #pragma unroll
    for (int g = 0; g < 3; g++)
        #pragma unroll
        for (int t = 0; t < 2; t++)
            #pragma unroll
            for (int q = 0; q < 4; q++) acc[g][t][q] = 0.f;

    #pragma unroll 2
    for (int ks = 0; ks < 12; ks++) {
        const int k = ks * 16 + qc;
        unsigned a[3][4];
        #pragma unroll
        for (int g = 0; g < 3; g++) {
            int r = g * 16 + qr;
            a[g][0] = *(const unsigned*)&sW[r * 200 + k];
            a[g][1] = *(const unsigned*)&sW[(r + 8) * 200 + k];
            a[g][2] = *(const unsigned*)&sW[r * 200 + k + 8];
            a[g][3] = *(const unsigned*)&sW[(r + 8) * 200 + k + 8];
        }
        unsigned bf[2][2];
        #pragma unroll
        for (int tg = 0; tg < 2; tg++) {
            const __half* xp = X + (size_t)k * LL + tB + tg * 8;
            bf[tg][0] = pack2(xp[0], xp[LL]);
            bf[tg][1] = pack2(xp[8 * LL], xp[9 * LL]);
        }
        #pragma unroll
        for (int g = 0; g < 3; g++)
            #pragma unroll
            for (int tg = 0; tg < 2; tg++)
                mma16816(acc[g][tg], a[g], bf[tg]);
    }

    #pragma unroll
    for (int g = 0; g < 3; g++) {
        #pragma unroll
        for (int tg = 0; tg < 2; tg++) {
            int T = m0 + w * 16 + tg * 8 + qc;
            #pragma unroll
            for (int q = 0; q < 4; q++) {
                int nb = g * 16 + qr + ((q >= 2) ? 8 : 0);
                int Tt = T + (q & 1);
                float v = acc[g][tg][q];
                if (nb < RNK)        g_dtm[(size_t)Tt * RNK + nb] = v;
                else if (nb < 38)    g_BC[(size_t)Tt * 32 + (nb - RNK)] = v;
            }
        }
    }
}

// ---------------- out_proj via tensor cores ----------------
__global__ void __launch_bounds__(128) outproj_mma(float* __restrict__ out)
{
    __shared__ __half sA[64 * 200];
    const int tid = threadIdx.x;
    const int w = tid >> 5, lane = tid & 31;
    const int m0 = blockIdx.x * 64;
    const int b = m0 >> 12, p0 = m0 & 4095;

    for (int i = tid; i < 64 * 48; i += 128) {
        int m = i / 48, kq = (i - m * 48) * 4;
        float4 yv = *(const float4*)&g_ycomb[(size_t)(m0 + m) * 192 + kq];
        float4 zv = *(const float4*)&g_zs[(size_t)(m0 + m) * 192 + kq];
        *(__half2*)&sA[m * 200 + kq]     = __floats2half2_rn(yv.x * zv.x, yv.y * zv.y);
        *(__half2*)&sA[m * 200 + kq + 2] = __floats2half2_rn(yv.z * zv.z, yv.w * zv.w);
    }
    __syncthreads();

    const int qr = lane >> 2, qc = (lane & 3) << 1;
    const int rA = w * 16 + qr;

    float acc[12][4];
    #pragma unroll
    for (int g = 0; g < 12; g++)
        #pragma unroll
        for (int q = 0; q < 4; q++) acc[g][q] = 0.f;

    for (int ks = 0; ks < 12; ks++) {
        const int k = ks * 16 + qc;
        unsigned a[4];
        a[0] = *(const unsigned*)&sA[rA * 200 + k];
        a[1] = *(const unsigned*)&sA[(rA + 8) * 200 + k];
        a[2] = *(const unsigned*)&sA[rA * 200 + k + 8];
        a[3] = *(const unsigned*)&sA[(rA + 8) * 200 + k + 8];
        #pragma unroll
        for (int g = 0; g < 12; g++) {
            int n = g * 8 + qr;
            unsigned bf[2];
            bf[0] = *(const unsigned*)&g_Wh2[n * 192 + k];
            bf[1] = *(const unsigned*)&g_Wh2[n * 192 + k + 8];
            mma16816(acc[g], a, bf);
        }
    }

    #pragma unroll
    for (int g = 0; g < 12; g++) {
        int nc = g * 8 + qc;
        int t = p0 + w * 16 + qr;
        out[((size_t)b * 96 + nc)     * 4096 + t]     = acc[g][0];
        out[((size_t)b * 96 + nc + 1) * 4096 + t]     = acc[g][1];
        out[((size_t)b * 96 + nc)     * 4096 + t + 8] = acc[g][2];
        out[((size_t)b * 96 + nc + 1) * 4096 + t + 8] = acc[g][3];
    }
}

// ---------------- chunked selective scan (dt_proj fused into staging) ----------------
__global__ void __launch_bounds__(128) scanA_kernel(const float* __restrict__ A_log,
    const float* __restrict__ dtw, const float* __restrict__ dtb)
{
    __shared__ float2 sdu[16][CT + 2];
    __shared__ float2 sB[CT][8];
    __shared__ float sdt[RNK][CT + 2];
    __shared__ float swr[16][RNK];
    __shared__ float sbias[16];
    const int tid = threadIdx.x;
    const int c = blockIdx.x, dg = blockIdx.y, n = blockIdx.z;
    const int l0 = c * CT, d0 = dg * 16;

    {
        const float* src = g_dtm + ((size_t)n * LL + l0) * RNK;
        for (int i = tid; i < CT * RNK; i += 128) {
            int l = i / RNK, r = i - l * RNK;
            sdt[r][l] = src[i];
        }
    }
    if (tid < 16 * RNK) swr[tid / RNK][tid % RNK] = dtw[(d0 + tid / RNK) * RNK + tid % RNK];
    else if (tid >= 112) sbias[tid - 112] = dtb[d0 + tid - 112];
    for (int i = tid; i < CT * 8; i += 128) {
        int l = i >> 3, j = i & 7;
        sB[l][j] = *(const float2*)&g_BC[((size_t)n * LL + l0 + l) * 32 + 2 * j];
    }
    __syncthreads();

    for (int i = tid; i < 16 * (CT / 2); i += 128) {
        int dd = i >> 5, l2 = (i & 31) << 1;
        size_t off = (size_t)n * DI * LL + (size_t)(d0 + dd) * LL + l0 + l2;
        float2 fu = __half22float2(*(const __half2*)(g_xcT + off));
        float s0 = sbias[dd], s1 = s0;
        #pragma unroll
        for (int r = 0; r < RNK; r++) {
            float wv = swr[dd][r];
            s0 += sdt[r][l2] * wv;
            s1 += sdt[r][l2 + 1] * wv;
        }
        sdu[dd][l2]     = make_float2(softplus_f(s0), fu.x);
        sdu[dd][l2 + 1] = make_float2(softplus_f(s1), fu.y);
    }
    const int lane = tid & 31, w = tid >> 5;
    const int j = lane & 7, dloc = (w << 2) | (lane >> 3);
    const int d = d0 + dloc;
    float2 al = *(const float2*)&A_log[d * DS + 2 * j];
    const float cA0 = -expf(al.x) * 1.4426950408889634f;
    const float cA1 = -expf(al.y) * 1.4426950408889634f;
    __syncthreads();

    float h0 = 0.f, h1 = 0.f, S = 0.f;
    #pragma unroll 4
    for (int l = 0; l < CT; ++l) {
        float2 du = sdu[dloc][l];
        float2 Bv = sB[l][j];
        float a0 = ex2(du.x * cA0);
        float a1 = ex2(du.x * cA1);
        float du2 = du.x * du.y;
        h0 = a0 * h0 + du2 * Bv.x;
        h1 = a1 * h1 + du2 * Bv.y;
        S += du.x;
    }
    size_t o = ((size_t)(n * NC + c)) * (DI * DS) + d * DS + 2 * j;
    *(float2*)&g_H[o] = make_float2(h0, h1);
    *(float2*)&g_P[o] = make_float2(ex2(cA0 * S), ex2(cA1 * S));
}

__global__ void __launch_bounds__(256) scanB_kernel()
{
    const int gid = blockIdx.x * 256 + threadIdx.x;
    const int n = gid / (DI * DS);
    const int ds = gid - n * (DI * DS);
    size_t base = (size_t)n * NC * (DI * DS) + ds;
    float h = 0.f;
    #pragma unroll 4
    for (int cc = 0; cc < NC; ++cc) {
        size_t a = base + (size_t)cc * (DI * DS);
        float Pv = g_P[a], Hv = g_H[a];
        g_H[a] = h;
        h = Pv * h + Hv;
    }
}

__global__ void __launch_bounds__(128) scanC_kernel(
    const float* __restrict__ A_log, const float* __restrict__ Dp,
    const float* __restrict__ dtw, const float* __restrict__ dtb)
{
    __shared__ float2 sdu[16][CT + 2];
    __shared__ float2 sB[CT][8];
    __shared__ float2 sC[CT][8];
    __shared__ float sg[CT];
    __shared__ float sv[CT][16];
    __shared__ int sp[CT];
    __shared__ float sdt[RNK][CT + 2];
    __shared__ float swr[16][RNK];
    __shared__ float sbias[16];
    const int tid = threadIdx.x;
    const int c = blockIdx.x, dg = blockIdx.y, n = blockIdx.z;
    const int l0 = c * CT, d0 = dg * 16;
    const int b = n & 3, k = n >> 2;

    {
        const float* src = g_dtm + ((size_t)n * LL + l0) * RNK;
        for (int i = tid; i < CT * RNK; i += 128) {
            int l = i / RNK, r = i - l * RNK;
            sdt[r][l] = src[i];
        }
    }
    if (tid < 16 * RNK) swr[tid / RNK][tid % RNK] = dtw[(d0 + tid / RNK) * RNK + tid % RNK];
    else if (tid >= 112) sbias[tid - 112] = dtb[d0 + tid - 112];
    for (int i = tid; i < CT * 8; i += 128) {
        int l = i >> 3, j = i & 7;
        const float* bc = &g_BC[((size_t)n * LL + l0 + l) * 32];
        sB[l][j] = *(const float2*)(bc + 2 * j);
        sC[l][j] = *(const float2*)(bc + 16 + 2 * j);
    }
    if (tid < CT) {
        sp[tid] = pmap(l0 + tid, k);
        sg[tid] = g_gateT[(size_t)n * LL + l0 + tid];
    }
    __syncthreads();

    for (int i = tid; i < 16 * (CT / 2); i += 128) {
        int dd = i >> 5, l2 = (i & 31) << 1;
        size_t off = (size_t)n * DI * LL + (size_t)(d0 + dd) * LL + l0 + l2;
        float2 fu = __half22float2(*(const __half2*)(g_xcT + off));
        float s0 = sbias[dd], s1 = s0;
        #pragma unroll
        for (int r = 0; r < RNK; r++) {
            float wv = swr[dd][r];
            s0 += sdt[r][l2] * wv;
            s1 += sdt[r][l2 + 1] * wv;
        }
        sdu[dd][l2]     = make_float2(softplus_f(s0), fu.x);
        sdu[dd][l2 + 1] = make_float2(softplus_f(s1), fu.y);
    }
    const int lane = tid & 31, w = tid >> 5;
    const int j = lane & 7, dloc = (w << 2) | (lane >> 3);
    const int d = d0 + dloc;
    float2 al = *(const float2*)&A_log[d * DS + 2 * j];
    const float cA0 = -expf(al.x) * 1.4426950408889634f;
    const float cA1 = -expf(al.y) * 1.4426950408889634f;
    const float Dd = Dp[d];
    __syncthreads();

    float2 hv = *(const float2*)&g_H[((size_t)(n * NC + c)) * (DI * DS) + d * DS + 2 * j];
    float h0 = hv.x, h1 = hv.y;

    #pragma unroll 4
    for (int l = 0; l < CT; ++l) {
        float2 du = sdu[dloc][l];
        float2 Bv = sB[l][j];
        float2 Cv = sC[l][j];
        float a0 = ex2(du.x * cA0);
        float a1 = ex2(du.x * cA1);
        float du2 = du.x * du.y;
        h0 = a0 * h0 + du2 * Bv.x;
        h1 = a1 * h1 + du2 * Bv.y;
        float y = h0 * Cv.x + h1 * Cv.y;
        y += __shfl_xor_sync(0xffffffffu, y, 1);
        y += __shfl_xor_sync(0xffffffffu, y, 2);
        y += __shfl_xor_sync(0xffffffffu, y, 4);
        if (j == 0)
            sv[l][dloc] = (y + du.y * Dd) * sg[l];
    }
    __syncthreads();

    float* ycb = g_ycomb + (size_t)b * LL * DI + d0;
    #pragma unroll
    for (int jj = 0; jj < 8; jj++) {
        int i = tid + jj * 128;
        int dd = i & 15, l = i >> 4;
        atomicAdd(ycb + (size_t)sp[l] * DI + dd, sv[l][dd]);
    }
}

// ---------------- launch ----------------
extern "C" void kernel_launch(void* const* d_in, const int* in_sizes, int n_in,
                              void* d_out, int out_size)
{
    const float* x         = (const float*)d_in[0];
    const float* norm_g    = (const float*)d_in[1];
    const float* norm_b    = (const float*)d_in[2];
    const float* gate_w1   = (const float*)d_in[3];
    const float* gate_b1   = (const float*)d_in[4];
    const float* gate_w2   = (const float*)d_in[5];
    const float* gate_b2   = (const float*)d_in[6];
    const float* in_proj_w = (const float*)d_in[7];
    const float* conv_w    = (const float*)d_in[8];
    const float* conv_b    = (const float*)d_in[9];
    const float* x_proj_w  = (const float*)d_in[10];
    const float* dt_proj_w = (const float*)d_in[11];
    const float* dt_proj_b = (const float*)d_in[12];
    const float* A_log     = (const float*)d_in[13];
    const float* Dvec      = (const float*)d_in[14];
    const float* out_proj_w= (const float*)d_in[15];
    float* out = (float*)d_out;

    norm_gate_kernel<<<512, 128>>>(x, norm_g, norm_b, gate_w1, gate_b1, gate_w2, gate_b2,
                                   x_proj_w, out_proj_w, in_proj_w);
    inproj_mma<<<256, 256>>>();
    conv_kernel<<<dim3(LL / CONV_TL, NDIR), 192>>>(conv_w, conv_b);
    xproj_mma<<<1024, 128>>>();
    scanA_kernel<<<dim3(NC, 12, NDIR), 128>>>(A_log, dt_proj_w, dt_proj_b);
    scanB_kernel<<<(NDIR * DI * DS) / 256, 256>>>();
    scanC_kernel<<<dim3(NC, 12, NDIR), 128>>>(A_log, Dvec, dt_proj_w, dt_proj_b);
    outproj_mma<<<256, 128>>>(out);
}